// round 8
// baseline (speedup 1.0000x reference)
#include <cuda_runtime.h>
#include <math.h>

#define BB    16
#define TT    64
#define IND   256
#define HH    512
#define NN    256
#define WWD   64
#define RR    4
#define OUTD  256
#define ITFD  471

// interface vector offsets
#define O_RK 0
#define O_RS 256
#define O_WK 260
#define O_WS 324
#define O_ER 325
#define O_WV 389
#define O_FG 453
#define O_AG 457
#define O_WG 458
#define O_MO 459
#define EPSF 1e-6f

// -------------------- persistent state (device globals) --------------------
__device__ float g_h[2][BB * HH];
__device__ float g_c[BB * HH];
__device__ float g_M[BB * NN * WWD];
__device__ float g_usage[BB * NN];
__device__ float g_link[BB * NN * NN];
__device__ float g_prec[BB * NN];
__device__ float g_wr[BB * RR * NN];
__device__ float g_ww[BB * NN];
__device__ float g_rw[BB * RR * WWD];
__device__ float g_itf[BB * ITFD];
__device__ float g_hall[TT * BB * HH];
__device__ float g_rwall[TT * BB * RR * WWD];
__device__ float g_WintT[ITFD * HH];

// -------------------- helpers --------------------
__device__ __forceinline__ float sigf(float x) { return 1.f / (1.f + expf(-x)); }
__device__ __forceinline__ float softplusf(float x) {
    return fmaxf(x, 0.f) + log1pf(expf(-fabsf(x)));
}
__device__ __forceinline__ float oneplusf(float x) { return 1.f + softplusf(x); }

__device__ __forceinline__ float blk_max256(float v, float* red, int tid) {
    red[tid] = v; __syncthreads();
    for (int s = 128; s > 0; s >>= 1) {
        if (tid < s) red[tid] = fmaxf(red[tid], red[tid + s]);
        __syncthreads();
    }
    float r = red[0]; __syncthreads();
    return r;
}
__device__ __forceinline__ float blk_sum256(float v, float* red, int tid) {
    red[tid] = v; __syncthreads();
    for (int s = 128; s > 0; s >>= 1) {
        if (tid < s) red[tid] = red[tid] + red[tid + s];
        __syncthreads();
    }
    float r = red[0]; __syncthreads();
    return r;
}

// -------------------- K0: transpose W_int (round-1 verbatim) --------------------
__global__ void k_transpose(const float* __restrict__ Wint) {
    int idx = blockIdx.x * 256 + threadIdx.x;
    if (idx < ITFD * HH) {
        int c = idx / HH;
        int k = idx - c * HH;
        g_WintT[idx] = Wint[k * ITFD + c];
    }
}

// -------------------- K1: fused LSTM (round-1 verbatim) --------------------
// grid 128, block 256. Block handles 4 j values; tid = jj*64 + kc*16 + b.
__global__ void k_lstm(const float* __restrict__ x,
                       const float* __restrict__ Wih,
                       const float* __restrict__ Whh,
                       const float* __restrict__ bih,
                       const float* __restrict__ bhh,
                       int t, int hp) {
    int tid = threadIdx.x;
    int jj = tid >> 6;
    int kc = (tid >> 4) & 3;
    int b  = tid & 15;
    int j  = blockIdx.x * 4 + jj;

    const float* hprev = g_h[hp];
    const float* src;
    if (kc < 2) src = x + ((size_t)t * BB + b) * IND + kc * 128;
    else        src = g_rw + b * (RR * WWD) + (kc - 2) * 128;

    float ai = 0.f, af = 0.f, ag = 0.f, ao = 0.f;
    {
        const float* wi = Wih + ((size_t)(0 * HH + j)) * 512 + kc * 128;
        const float* wf = Wih + ((size_t)(1 * HH + j)) * 512 + kc * 128;
        const float* wg = Wih + ((size_t)(2 * HH + j)) * 512 + kc * 128;
        const float* wo = Wih + ((size_t)(3 * HH + j)) * 512 + kc * 128;
        #pragma unroll 8
        for (int kk = 0; kk < 128; kk++) {
            float v = src[kk];
            ai += v * wi[kk]; af += v * wf[kk]; ag += v * wg[kk]; ao += v * wo[kk];
        }
    }
    {
        const float* hs = hprev + b * HH + kc * 128;
        const float* wi = Whh + ((size_t)(0 * HH + j)) * 512 + kc * 128;
        const float* wf = Whh + ((size_t)(1 * HH + j)) * 512 + kc * 128;
        const float* wg = Whh + ((size_t)(2 * HH + j)) * 512 + kc * 128;
        const float* wo = Whh + ((size_t)(3 * HH + j)) * 512 + kc * 128;
        #pragma unroll 8
        for (int kk = 0; kk < 128; kk++) {
            float v = hs[kk];
            ai += v * wi[kk]; af += v * wf[kk]; ag += v * wg[kk]; ao += v * wo[kk];
        }
    }
    __shared__ float sred[4][256];
    sred[0][tid] = ai; sred[1][tid] = af; sred[2][tid] = ag; sred[3][tid] = ao;
    __syncthreads();
    if (kc == 0) {
        int base = jj * 64 + b;
        float si = sred[0][base] + sred[0][base + 16] + sred[0][base + 32] + sred[0][base + 48];
        float sf = sred[1][base] + sred[1][base + 16] + sred[1][base + 32] + sred[1][base + 48];
        float sg = sred[2][base] + sred[2][base + 16] + sred[2][base + 32] + sred[2][base + 48];
        float so = sred[3][base] + sred[3][base + 16] + sred[3][base + 32] + sred[3][base + 48];
        float gi = si + bih[0 * HH + j] + bhh[0 * HH + j];
        float gf = sf + bih[1 * HH + j] + bhh[1 * HH + j];
        float gg = sg + bih[2 * HH + j] + bhh[2 * HH + j];
        float go = so + bih[3 * HH + j] + bhh[3 * HH + j];
        float cold = g_c[b * HH + j];
        float cn = sigf(gf) * cold + sigf(gi) * tanhf(gg);
        float hn = sigf(go) * tanhf(cn);
        g_c[b * HH + j] = cn;
        g_h[hp ^ 1][b * HH + j] = hn;
        g_hall[((size_t)t * BB + b) * HH + j] = hn;
    }
}

// -------------------- K2: interface GEMM (round-1 verbatim) --------------------
// grid 59, block 256. 8 cols per block; tid = cc*32 + kc*16 + b.
__global__ void k_itf(const float* __restrict__ bint, int hc) {
    int tid = threadIdx.x;
    int cc = tid >> 5;
    int lane = tid & 31;
    int kc = lane >> 4;
    int b = lane & 15;
    int c = blockIdx.x * 8 + cc;
    float acc = 0.f;
    if (c < ITFD) {
        const float* w = g_WintT + (size_t)c * HH + kc * 256;
        const float* h = g_h[hc] + b * HH + kc * 256;
        #pragma unroll 8
        for (int kk = 0; kk < 256; kk++) acc += h[kk] * w[kk];
    }
    acc += __shfl_xor_sync(0xffffffffu, acc, 16);
    if (c < ITFD && kc == 0) g_itf[b * ITFD + c] = acc + bint[c];
}

// -------------------- K3: fused write+mem+read (round-1 bodies concatenated) ----
// grid 16 (one block per batch), block 256.
__global__ void k_cde(int t) {
    int b = blockIdx.x;
    int tid = threadIdx.x;
    __shared__ float uval[NN];
    __shared__ int   uidx[NN];
    __shared__ float ps[NN];
    __shared__ float cw[NN];
    __shared__ float allocv[NN];
    __shared__ float red[NN];
    __shared__ float karr[WWD];
    __shared__ float sc_knorm, sc_beta;
    __shared__ float sww[NN];
    __shared__ float sprec[NN];
    __shared__ float kn[RR][WWD];
    __shared__ float wr_s[RR][NN];
    __shared__ float fwd[RR][NN];
    __shared__ float bwd[RR][NN];
    __shared__ float cr[RR][NN];
    __shared__ float betas[RR], knorm[RR], mbv[RR], mfv[RR], mcv[RR];

    const float* itf = g_itf + (size_t)b * ITFD;

    // stage wr_prev for the read stage (psi below reads global directly, as round 1 did)
    for (int idx = tid; idx < RR * NN; idx += 256)
        wr_s[idx >> 8][idx & 255] = g_wr[b * RR * NN + idx];

    // ======================= WRITE stage (round-1 k_write) =======================
    float fg0 = sigf(itf[O_FG + 0]);
    float fg1 = sigf(itf[O_FG + 1]);
    float fg2 = sigf(itf[O_FG + 2]);
    float fg3 = sigf(itf[O_FG + 3]);
    float ag  = sigf(itf[O_AG]);
    float wg  = sigf(itf[O_WG]);

    // usage update
    int n = tid;
    float psi = 1.f;
    psi *= (1.f - fg0 * g_wr[(b * RR + 0) * NN + n]);
    psi *= (1.f - fg1 * g_wr[(b * RR + 1) * NN + n]);
    psi *= (1.f - fg2 * g_wr[(b * RR + 2) * NN + n]);
    psi *= (1.f - fg3 * g_wr[(b * RR + 3) * NN + n]);
    float u = g_usage[b * NN + n];
    float wagg = g_ww[b * NN + n];  // NW=1 -> 1-(1-ww)=ww
    float un = (u + wagg - u * wagg) * psi;
    uval[tid] = un; uidx[tid] = tid;
    g_usage[b * NN + n] = un;

    if (tid < WWD) karr[tid] = itf[O_WK + tid];
    __syncthreads();
    if (tid == 0) {
        float ss = 0.f;
        for (int w = 0; w < WWD; w++) ss += karr[w] * karr[w];
        sc_knorm = sqrtf(ss) + EPSF;
        sc_beta  = oneplusf(itf[O_WS]);
    }
    __syncthreads();

    // content write scores (OLD memory)
    float dot = 0.f, ss = 0.f;
    float* Mrow = g_M + ((size_t)(b * NN) + n) * WWD;
    #pragma unroll 8
    for (int w = 0; w < WWD; w++) {
        float m = Mrow[w];
        dot += m * karr[w];
        ss += m * m;
    }
    float sim = (dot / sc_knorm) / (sqrtf(ss) + EPSF);
    float sco = sc_beta * sim;
    float mx = blk_max256(sco, red, tid);
    float e = expf(sco - mx);
    float sm = blk_sum256(e, red, tid);
    cw[tid] = e / sm;
    __syncthreads();

    // stable bitonic sort ascending on (uval, uidx) — round-1 verbatim
    for (int k2 = 2; k2 <= NN; k2 <<= 1) {
        for (int jmp = k2 >> 1; jmp > 0; jmp >>= 1) {
            __syncthreads();
            int ixj = tid ^ jmp;
            if (ixj > tid) {
                float v0 = uval[tid], v1 = uval[ixj];
                int i0 = uidx[tid], i1 = uidx[ixj];
                bool up = ((tid & k2) == 0);
                bool gt = (v0 > v1) || (v0 == v1 && i0 > i1);
                if (gt == up) {
                    uval[tid] = v1; uval[ixj] = v0;
                    uidx[tid] = i1; uidx[ixj] = i0;
                }
            }
        }
    }
    __syncthreads();

    // inclusive product scan of sorted usage — round-1 verbatim
    ps[tid] = uval[tid];
    __syncthreads();
    for (int off = 1; off < NN; off <<= 1) {
        float v = (tid >= off) ? ps[tid - off] : 1.f;
        __syncthreads();
        ps[tid] *= v;
        __syncthreads();
    }
    float excl = (tid > 0) ? ps[tid - 1] : 1.f;
    float a = (1.f - uval[tid]) * excl;
    allocv[uidx[tid]] = a;
    __syncthreads();

    float wwn = wg * (ag * allocv[tid] + (1.f - ag) * cw[tid]);
    sww[tid] = wwn;
    g_ww[b * NN + tid] = wwn;
    float wsum = blk_sum256(wwn, red, tid);
    sprec[tid] = g_prec[b * NN + tid];     // OLD precedence
    __syncthreads();

    // ======================= MEM stage (round-1 k_mem, per-batch) ================
    // link update: thread owns column j=tid, loops rows i.
    {
        float wwj = sww[tid];
        float prj = sprec[tid];
        float* lbase = g_link + (size_t)b * (NN * NN);
        #pragma unroll 4
        for (int i = 0; i < NN; i++) {
            float wwi = sww[i];
            float l = lbase[(size_t)i * NN + tid];
            float nv = (1.f - wwi - wwj) * l + wwi * prj;
            if (i == tid) nv = 0.f;
            lbase[(size_t)i * NN + tid] = nv;
        }
    }
    g_prec[b * NN + tid] = (1.f - wsum) * sprec[tid] + wwn;

    // memory erase/write: thread owns row n=tid (round-1 math)
    #pragma unroll 8
    for (int w = 0; w < WWD; w++) {
        float er = sigf(itf[O_ER + w]);
        float vv = sigf(itf[O_WV + w]);
        Mrow[w] = Mrow[w] * (1.f - wwn * er) + wwn * vv;
    }
    __syncthreads();   // link + M fully updated

    // ======================= READ stage (round-1 k_read) =========================
    {
        int r = tid >> 6, w = tid & 63;
        kn[r][w] = itf[O_RK + r * WWD + w];
    }
    __syncthreads();
    if (tid < RR) {
        float ss2 = 0.f;
        for (int w = 0; w < WWD; w++) ss2 += kn[tid][w] * kn[tid][w];
        knorm[tid] = sqrtf(ss2) + EPSF;
        betas[tid] = oneplusf(itf[O_RS + tid]);
        float m0 = itf[O_MO + tid * 3 + 0];
        float m1 = itf[O_MO + tid * 3 + 1];
        float m2 = itf[O_MO + tid * 3 + 2];
        float mxm = fmaxf(m0, fmaxf(m1, m2));
        float e0 = expf(m0 - mxm), e1 = expf(m1 - mxm), e2 = expf(m2 - mxm);
        float s = e0 + e1 + e2;
        mbv[tid] = e0 / s; mfv[tid] = e1 / s; mcv[tid] = e2 / s;
    }
    __syncthreads();

    // content read scores on NEW memory
    float d0 = 0.f, d1 = 0.f, d2 = 0.f, d3 = 0.f, ss2 = 0.f;
    #pragma unroll 8
    for (int w = 0; w < WWD; w++) {
        float m = Mrow[w];
        ss2 += m * m;
        d0 += m * kn[0][w]; d1 += m * kn[1][w]; d2 += m * kn[2][w]; d3 += m * kn[3][w];
    }
    float inv = 1.f / (sqrtf(ss2) + EPSF);
    float scv[4];
    scv[0] = betas[0] * (d0 / knorm[0]) * inv;
    scv[1] = betas[1] * (d1 / knorm[1]) * inv;
    scv[2] = betas[2] * (d2 / knorm[2]) * inv;
    scv[3] = betas[3] * (d3 / knorm[3]) * inv;
    for (int r = 0; r < RR; r++) {
        float mxr = blk_max256(scv[r], red, tid);
        float er = expf(scv[r] - mxr);
        float smr = blk_sum256(er, red, tid);
        cr[r][tid] = er / smr;
    }
    __syncthreads();

    // bwd[r][i] = sum_j link[b][j][i] * wr_prev[r][j]  (coalesced on i)
    {
        float a0 = 0.f, a1 = 0.f, a2 = 0.f, a3 = 0.f;
        for (int j = 0; j < NN; j++) {
            float lv = g_link[((size_t)(b * NN) + j) * NN + tid];
            a0 += lv * wr_s[0][j]; a1 += lv * wr_s[1][j];
            a2 += lv * wr_s[2][j]; a3 += lv * wr_s[3][j];
        }
        bwd[0][tid] = a0; bwd[1][tid] = a1; bwd[2][tid] = a2; bwd[3][tid] = a3;
    }
    // fwd[r][i] = sum_j link[b][i][j] * wr_prev[r][j]  (warp per row)
    {
        int warp = tid >> 5, lane = tid & 31;
        for (int rr = 0; rr < 32; rr++) {
            int i = warp * 32 + rr;
            const float* lrow = g_link + ((size_t)(b * NN) + i) * NN;
            float a0 = 0.f, a1 = 0.f, a2 = 0.f, a3 = 0.f;
            for (int j = lane; j < NN; j += 32) {
                float lv = lrow[j];
                a0 += lv * wr_s[0][j]; a1 += lv * wr_s[1][j];
                a2 += lv * wr_s[2][j]; a3 += lv * wr_s[3][j];
            }
            #pragma unroll
            for (int off = 16; off > 0; off >>= 1) {
                a0 += __shfl_down_sync(0xffffffffu, a0, off);
                a1 += __shfl_down_sync(0xffffffffu, a1, off);
                a2 += __shfl_down_sync(0xffffffffu, a2, off);
                a3 += __shfl_down_sync(0xffffffffu, a3, off);
            }
            if (lane == 0) { fwd[0][i] = a0; fwd[1][i] = a1; fwd[2][i] = a2; fwd[3][i] = a3; }
        }
    }
    __syncthreads();

    float wrn[4];
    #pragma unroll
    for (int r = 0; r < RR; r++)
        wrn[r] = mbv[r] * bwd[r][tid] + mfv[r] * fwd[r][tid] + mcv[r] * cr[r][tid];
    __syncthreads();
    #pragma unroll
    for (int r = 0; r < RR; r++) {
        wr_s[r][tid] = wrn[r];
        g_wr[(b * RR + r) * NN + tid] = wrn[r];
    }
    __syncthreads();

    // read_words[r][w] = sum_n wr[r][n] * M[b][n][w]
    {
        int r = tid >> 6, w = tid & 63;
        float acc = 0.f;
        for (int n2 = 0; n2 < NN; n2++)
            acc += wr_s[r][n2] * g_M[((size_t)(b * NN) + n2) * WWD + w];
        g_rw[(b * RR + r) * WWD + w] = acc;
        g_rwall[((size_t)t * BB + b) * (RR * WWD) + r * WWD + w] = acc;
    }
}

// -------------------- K6: batched output GEMM (round-1 verbatim) --------------------
__global__ void k_out(const float* __restrict__ Wout,
                      const float* __restrict__ bout,
                      float* __restrict__ out) {
    __shared__ float As[32][33];
    __shared__ float Bs[32][33];
    int tx = threadIdx.x & 15, ty = threadIdx.x >> 4;
    int tb0 = blockIdx.x * 32, o0 = blockIdx.y * 32;
    float acc00 = 0.f, acc01 = 0.f, acc10 = 0.f, acc11 = 0.f;
    for (int kt = 0; kt < 768; kt += 32) {
        for (int l = threadIdx.x; l < 1024; l += 256) {
            int mi = l >> 5, ki = l & 31;
            int k = kt + ki;
            int tb = tb0 + mi;
            float av = (k < 512) ? g_hall[(size_t)tb * HH + k]
                                 : g_rwall[(size_t)tb * (RR * WWD) + (k - 512)];
            As[mi][ki] = av;
            Bs[mi][ki] = Wout[(size_t)(o0 + mi) * 768 + k];
        }
        __syncthreads();
        #pragma unroll 8
        for (int ki = 0; ki < 32; ki++) {
            float a0 = As[ty * 2][ki], a1 = As[ty * 2 + 1][ki];
            float b0 = Bs[tx * 2][ki], b1 = Bs[tx * 2 + 1][ki];
            acc00 += a0 * b0; acc01 += a0 * b1;
            acc10 += a1 * b0; acc11 += a1 * b1;
        }
        __syncthreads();
    }
    int tb = tb0 + ty * 2, o = o0 + tx * 2;
    float bo0 = bout[o], bo1 = bout[o + 1];
    out[(size_t)tb * OUTD + o] = acc00 + bo0;
    out[(size_t)tb * OUTD + o + 1] = acc01 + bo1;
    out[(size_t)(tb + 1) * OUTD + o] = acc10 + bo0;
    out[(size_t)(tb + 1) * OUTD + o + 1] = acc11 + bo1;
}

// -------------------- host launch --------------------
extern "C" void kernel_launch(void* const* d_in, const int* in_sizes, int n_in,
                              void* d_out, int out_size) {
    const float* x    = (const float*)d_in[0];
    const float* Wih  = (const float*)d_in[1];
    const float* Whh  = (const float*)d_in[2];
    const float* bih  = (const float*)d_in[3];
    const float* bhh  = (const float*)d_in[4];
    const float* Wint = (const float*)d_in[5];
    const float* bint = (const float*)d_in[6];
    const float* Wout = (const float*)d_in[7];
    const float* bout = (const float*)d_in[8];
    float* out = (float*)d_out;

    void* p;
    cudaGetSymbolAddress(&p, g_h);     cudaMemsetAsync(p, 0, sizeof(float) * 2 * BB * HH);
    cudaGetSymbolAddress(&p, g_c);     cudaMemsetAsync(p, 0, sizeof(float) * BB * HH);
    cudaGetSymbolAddress(&p, g_M);     cudaMemsetAsync(p, 0, sizeof(float) * BB * NN * WWD);
    cudaGetSymbolAddress(&p, g_usage); cudaMemsetAsync(p, 0, sizeof(float) * BB * NN);
    cudaGetSymbolAddress(&p, g_link);  cudaMemsetAsync(p, 0, sizeof(float) * BB * NN * NN);
    cudaGetSymbolAddress(&p, g_prec);  cudaMemsetAsync(p, 0, sizeof(float) * BB * NN);
    cudaGetSymbolAddress(&p, g_wr);    cudaMemsetAsync(p, 0, sizeof(float) * BB * RR * NN);
    cudaGetSymbolAddress(&p, g_ww);    cudaMemsetAsync(p, 0, sizeof(float) * BB * NN);
    cudaGetSymbolAddress(&p, g_rw);    cudaMemsetAsync(p, 0, sizeof(float) * BB * RR * WWD);

    k_transpose<<<(ITFD * HH + 255) / 256, 256>>>(Wint);

    for (int t = 0; t < TT; t++) {
        int par = t & 1;
        k_lstm<<<128, 256>>>(x, Wih, Whh, bih, bhh, t, par);
        k_itf<<<59, 256>>>(bint, par ^ 1);
        k_cde<<<16, 256>>>(t);
    }
    k_out<<<dim3(32, 8), 256>>>(Wout, bout, out);
}

// round 9
// speedup vs baseline: 2.0462x; 2.0462x over previous
#include <cuda_runtime.h>
#include <math.h>

#define BB    16
#define TT    64
#define IND   256
#define HH    512
#define NN    256
#define WWD   64
#define RR    4
#define OUTD  256
#define ITFD  471

// interface vector offsets
#define O_RK 0
#define O_RS 256
#define O_WK 260
#define O_WS 324
#define O_ER 325
#define O_WV 389
#define O_FG 453
#define O_AG 457
#define O_WG 458
#define O_MO 459
#define EPSF 1e-6f

// -------------------- persistent state --------------------
__device__ __align__(16) float g_h[2][BB * HH];
__device__ __align__(16) float g_c[BB * HH];
__device__ __align__(16) float g_M[BB * NN * WWD];
__device__ __align__(16) float g_usage[BB * NN];
__device__ __align__(16) float g_link[BB * NN * NN];
__device__ __align__(16) float g_prec[2][BB * NN];
__device__ __align__(16) float g_wr[BB * RR * NN];
__device__ __align__(16) float g_ww[BB * NN];
__device__ __align__(16) float g_rw[BB * RR * WWD];
__device__ __align__(16) float g_itf[BB * ITFD];
__device__ __align__(16) float g_hall[TT * BB * HH];
__device__ __align__(16) float g_rwall[TT * BB * RR * WWD];
__device__ __align__(16) float g_WintT[ITFD * HH];
__device__ __align__(16) float g_bwdP[BB * 16 * RR * NN];  // per-chunk bwd partials
__device__ __align__(16) float g_fwd[BB * RR * NN];

// -------------------- helpers --------------------
__device__ __forceinline__ float sigf(float x) { return 1.f / (1.f + expf(-x)); }
__device__ __forceinline__ float softplusf(float x) {
    return fmaxf(x, 0.f) + log1pf(expf(-fabsf(x)));
}
__device__ __forceinline__ float oneplusf(float x) { return 1.f + softplusf(x); }

// verified smem-tree reductions (round-8)
__device__ __forceinline__ float blk_max256(float v, float* red, int tid) {
    red[tid] = v; __syncthreads();
    for (int s = 128; s > 0; s >>= 1) {
        if (tid < s) red[tid] = fmaxf(red[tid], red[tid + s]);
        __syncthreads();
    }
    float r = red[0]; __syncthreads();
    return r;
}
__device__ __forceinline__ float blk_sum256(float v, float* red, int tid) {
    red[tid] = v; __syncthreads();
    for (int s = 128; s > 0; s >>= 1) {
        if (tid < s) red[tid] = red[tid] + red[tid + s];
        __syncthreads();
    }
    float r = red[0]; __syncthreads();
    return r;
}

// block reduce 4 values at once (shfl + smem), results broadcast in v[]
__device__ __forceinline__ void red4op(float v[4], bool domax, volatile float* red) {
    int tid = threadIdx.x;
    #pragma unroll
    for (int r = 0; r < 4; r++)
        #pragma unroll
        for (int o = 16; o; o >>= 1) {
            float u = __shfl_xor_sync(0xffffffffu, v[r], o);
            v[r] = domax ? fmaxf(v[r], u) : (v[r] + u);
        }
    if ((tid & 31) == 0) {
        int w = tid >> 5;
        red[w * 4 + 0] = v[0]; red[w * 4 + 1] = v[1];
        red[w * 4 + 2] = v[2]; red[w * 4 + 3] = v[3];
    }
    __syncthreads();
    if (tid == 0) {
        #pragma unroll
        for (int r = 0; r < 4; r++) {
            float a = red[r];
            for (int w = 1; w < 8; w++) {
                float u = red[w * 4 + r];
                a = domax ? fmaxf(a, u) : (a + u);
            }
            red[40 + r] = a;
        }
    }
    __syncthreads();
    v[0] = red[40]; v[1] = red[41]; v[2] = red[42]; v[3] = red[43];
    __syncthreads();
}

// -------------------- K0: transpose W_int (verbatim) --------------------
__global__ void k_transpose(const float* __restrict__ Wint) {
    int idx = blockIdx.x * 256 + threadIdx.x;
    if (idx < ITFD * HH) {
        int c = idx / HH;
        int k = idx - c * HH;
        g_WintT[idx] = Wint[k * ITFD + c];
    }
}

// -------------------- K1: fused LSTM (round-1 verbatim) --------------------
__global__ void k_lstm(const float* __restrict__ x,
                       const float* __restrict__ Wih,
                       const float* __restrict__ Whh,
                       const float* __restrict__ bih,
                       const float* __restrict__ bhh,
                       int t, int hp) {
    int tid = threadIdx.x;
    int jj = tid >> 6;
    int kc = (tid >> 4) & 3;
    int b  = tid & 15;
    int j  = blockIdx.x * 4 + jj;

    const float* hprev = g_h[hp];
    const float* src;
    if (kc < 2) src = x + ((size_t)t * BB + b) * IND + kc * 128;
    else        src = g_rw + b * (RR * WWD) + (kc - 2) * 128;

    float ai = 0.f, af = 0.f, ag = 0.f, ao = 0.f;
    {
        const float* wi = Wih + ((size_t)(0 * HH + j)) * 512 + kc * 128;
        const float* wf = Wih + ((size_t)(1 * HH + j)) * 512 + kc * 128;
        const float* wg = Wih + ((size_t)(2 * HH + j)) * 512 + kc * 128;
        const float* wo = Wih + ((size_t)(3 * HH + j)) * 512 + kc * 128;
        #pragma unroll 8
        for (int kk = 0; kk < 128; kk++) {
            float v = src[kk];
            ai += v * wi[kk]; af += v * wf[kk]; ag += v * wg[kk]; ao += v * wo[kk];
        }
    }
    {
        const float* hs = hprev + b * HH + kc * 128;
        const float* wi = Whh + ((size_t)(0 * HH + j)) * 512 + kc * 128;
        const float* wf = Whh + ((size_t)(1 * HH + j)) * 512 + kc * 128;
        const float* wg = Whh + ((size_t)(2 * HH + j)) * 512 + kc * 128;
        const float* wo = Whh + ((size_t)(3 * HH + j)) * 512 + kc * 128;
        #pragma unroll 8
        for (int kk = 0; kk < 128; kk++) {
            float v = hs[kk];
            ai += v * wi[kk]; af += v * wf[kk]; ag += v * wg[kk]; ao += v * wo[kk];
        }
    }
    __shared__ float sred[4][256];
    sred[0][tid] = ai; sred[1][tid] = af; sred[2][tid] = ag; sred[3][tid] = ao;
    __syncthreads();
    if (kc == 0) {
        int base = jj * 64 + b;
        float si = sred[0][base] + sred[0][base + 16] + sred[0][base + 32] + sred[0][base + 48];
        float sf = sred[1][base] + sred[1][base + 16] + sred[1][base + 32] + sred[1][base + 48];
        float sg = sred[2][base] + sred[2][base + 16] + sred[2][base + 32] + sred[2][base + 48];
        float so = sred[3][base] + sred[3][base + 16] + sred[3][base + 32] + sred[3][base + 48];
        float gi = si + bih[0 * HH + j] + bhh[0 * HH + j];
        float gf = sf + bih[1 * HH + j] + bhh[1 * HH + j];
        float gg = sg + bih[2 * HH + j] + bhh[2 * HH + j];
        float go = so + bih[3 * HH + j] + bhh[3 * HH + j];
        float cold = g_c[b * HH + j];
        float cn = sigf(gf) * cold + sigf(gi) * tanhf(gg);
        float hn = sigf(go) * tanhf(cn);
        g_c[b * HH + j] = cn;
        g_h[hp ^ 1][b * HH + j] = hn;
        g_hall[((size_t)t * BB + b) * HH + j] = hn;
    }
}

// -------------------- K2: fused interface GEMV + write addressing --------------
// grid 16 (one block per batch), block 256.
__global__ void __launch_bounds__(256) k_itfw(const float* __restrict__ bint, int par) {
    int b = blockIdx.x;
    int tid = threadIdx.x;
    __shared__ float hS[HH];
    __shared__ float itfs[ITFD + 1];
    __shared__ float uval[NN];
    __shared__ int   uidx[NN];
    __shared__ float allocv[NN];
    __shared__ float red[NN];
    __shared__ float karr[WWD];
    __shared__ float sc_knorm, sc_beta;

    // stage new h
    for (int i = tid; i < HH; i += 256) hS[i] = g_h[par ^ 1][b * HH + i];
    __syncthreads();

    // interface GEMV: warp per output, stride 8
    {
        int warp = tid >> 5, lane = tid & 31;
        const float4* h4 = (const float4*)hS;
        for (int c = warp; c < ITFD; c += 8) {
            const float4* w4 = (const float4*)(g_WintT + (size_t)c * HH);
            float acc = 0.f;
            #pragma unroll
            for (int q = 0; q < 4; q++) {
                float4 wv = w4[lane + q * 32];
                float4 hv = h4[lane + q * 32];
                acc += wv.x * hv.x + wv.y * hv.y + wv.z * hv.z + wv.w * hv.w;
            }
            #pragma unroll
            for (int o = 16; o; o >>= 1) acc += __shfl_xor_sync(0xffffffffu, acc, o);
            if (lane == 0) {
                float v = acc + bint[c];
                itfs[c] = v;
                g_itf[b * ITFD + c] = v;
            }
        }
    }
    __syncthreads();

    // ---------------- write addressing (round-8 math) ----------------
    float fg0 = sigf(itfs[O_FG + 0]);
    float fg1 = sigf(itfs[O_FG + 1]);
    float fg2 = sigf(itfs[O_FG + 2]);
    float fg3 = sigf(itfs[O_FG + 3]);
    float ag  = sigf(itfs[O_AG]);
    float wg  = sigf(itfs[O_WG]);

    // usage update
    int n = tid;
    float psi = 1.f;
    psi *= (1.f - fg0 * g_wr[(b * RR + 0) * NN + n]);
    psi *= (1.f - fg1 * g_wr[(b * RR + 1) * NN + n]);
    psi *= (1.f - fg2 * g_wr[(b * RR + 2) * NN + n]);
    psi *= (1.f - fg3 * g_wr[(b * RR + 3) * NN + n]);
    float u = g_usage[b * NN + n];
    float wagg = g_ww[b * NN + n];  // NW=1
    float un = (u + wagg - u * wagg) * psi;
    g_usage[b * NN + n] = un;

    if (tid < WWD) karr[tid] = itfs[O_WK + tid];
    __syncthreads();
    if (tid == 0) {
        float ss = 0.f;
        for (int w = 0; w < WWD; w++) ss += karr[w] * karr[w];
        sc_knorm = sqrtf(ss) + EPSF;
        sc_beta  = oneplusf(itfs[O_WS]);
    }
    __syncthreads();

    // content write scores (OLD memory)
    float dot = 0.f, ss = 0.f;
    const float* Mrow = g_M + ((size_t)(b * NN) + n) * WWD;
    #pragma unroll 8
    for (int w = 0; w < WWD; w++) {
        float m = Mrow[w];
        dot += m * karr[w];
        ss += m * m;
    }
    float sim = (dot / sc_knorm) / (sqrtf(ss) + EPSF);
    float sco = sc_beta * sim;
    float mx = blk_max256(sco, red, tid);
    float e = expf(sco - mx);
    float sm = blk_sum256(e, red, tid);
    float cwv = e / sm;

    // stable bitonic sort ascending on (usage, index); shfl for jmp<32
    float v = un; int ix = tid;
    for (int k2 = 2; k2 <= NN; k2 <<= 1) {
        for (int jmp = k2 >> 1; jmp; jmp >>= 1) {
            bool up = ((tid & k2) == 0);
            float v2; int i2;
            if (jmp >= 32) {
                uval[tid] = v; uidx[tid] = ix;
                __syncthreads();
                v2 = uval[tid ^ jmp]; i2 = uidx[tid ^ jmp];
                __syncthreads();
            } else {
                v2 = __shfl_xor_sync(0xffffffffu, v, jmp);
                i2 = __shfl_xor_sync(0xffffffffu, ix, jmp);
            }
            bool lower = ((tid & jmp) == 0);
            bool iless = (v < v2) || (v == v2 && ix < i2);
            bool keep = (iless == (lower == up));
            if (!keep) { v = v2; ix = i2; }
        }
    }

    // exclusive product scan over sorted usage -> allocation
    {
        int lane = tid & 31, wid = tid >> 5;
        float p = v;
        #pragma unroll
        for (int o = 1; o < 32; o <<= 1) {
            float q = __shfl_up_sync(0xffffffffu, p, o);
            if (lane >= o) p *= q;
        }
        if (lane == 31) red[wid] = p;
        __syncthreads();
        if (tid == 0) {
            float a = 1.f;
            #pragma unroll
            for (int w = 0; w < 8; w++) { float q = red[w]; red[8 + w] = a; a *= q; }
        }
        __syncthreads();
        float tmp = __shfl_up_sync(0xffffffffu, p, 1);   // uniform shfl
        float exclw = (lane == 0) ? 1.f : tmp;
        float excl = red[8 + wid] * exclw;
        allocv[ix] = (1.f - v) * excl;
        __syncthreads();
    }

    // write weighting + precedence (ping-pong)
    float wwn = wg * (ag * allocv[tid] + (1.f - ag) * cwv);
    g_ww[b * NN + tid] = wwn;
    float wsum = blk_sum256(wwn, red, tid);
    float pold = g_prec[par][b * NN + tid];
    g_prec[par ^ 1][b * NN + tid] = (1.f - wsum) * pold + wwn;
}

// -------------------- K3: wide link+M update with fused bwd/fwd ----------------
// grid 256 = 16 batches x 16 row-chunks; block 256.
__global__ void __launch_bounds__(256) k_mem2(int par) {
    int blk = blockIdx.x;
    int b = blk >> 4, ch = blk & 15;
    int tid = threadIdx.x;
    __shared__ float sww[NN];
    __shared__ float sprec[NN];
    __shared__ float wr4[4][NN];
    __shared__ float er[WWD];
    __shared__ float vv[WWD];
    __shared__ float tile[16][260];

    sww[tid]   = g_ww[b * NN + tid];
    sprec[tid] = g_prec[par][b * NN + tid];   // OLD precedence
    #pragma unroll
    for (int r = 0; r < RR; r++) wr4[r][tid] = g_wr[(b * RR + r) * NN + tid];
    if (tid < WWD) {
        er[tid] = sigf(g_itf[b * ITFD + O_ER + tid]);
        vv[tid] = sigf(g_itf[b * ITFD + O_WV + tid]);
    }
    __syncthreads();

    // link update for rows [ch*16, ch*16+16); thread owns column j=tid.
    // Fused bwd partials: bp[r][tid] += nv * wr_prev[r][row]
    float wwj = sww[tid];
    float prj = sprec[tid];
    float bp0 = 0.f, bp1 = 0.f, bp2 = 0.f, bp3 = 0.f;
    float* lbase = g_link + (size_t)b * (NN * NN);
    #pragma unroll 4
    for (int ii = 0; ii < 16; ii++) {
        int i = ch * 16 + ii;
        float wwi = sww[i];
        float l = lbase[(size_t)i * NN + tid];
        float nv = (1.f - wwi - wwj) * l + wwi * prj;
        if (i == tid) nv = 0.f;
        lbase[(size_t)i * NN + tid] = nv;
        tile[ii][tid] = nv;
        bp0 += nv * wr4[0][i];
        bp1 += nv * wr4[1][i];
        bp2 += nv * wr4[2][i];
        bp3 += nv * wr4[3][i];
    }
    g_bwdP[((b * 16 + ch) * 4 + 0) * NN + tid] = bp0;
    g_bwdP[((b * 16 + ch) * 4 + 1) * NN + tid] = bp1;
    g_bwdP[((b * 16 + ch) * 4 + 2) * NN + tid] = bp2;
    g_bwdP[((b * 16 + ch) * 4 + 3) * NN + tid] = bp3;
    __syncthreads();

    // fwd for own rows: 8 warps x 2 rows
    {
        int warp = tid >> 5, lane = tid & 31;
        #pragma unroll
        for (int q = 0; q < 2; q++) {
            int ii = warp * 2 + q;
            int i = ch * 16 + ii;
            float a0 = 0.f, a1 = 0.f, a2 = 0.f, a3 = 0.f;
            #pragma unroll
            for (int p = 0; p < 8; p++) {
                int j = lane + p * 32;
                float lv = tile[ii][j];
                a0 += lv * wr4[0][j]; a1 += lv * wr4[1][j];
                a2 += lv * wr4[2][j]; a3 += lv * wr4[3][j];
            }
            #pragma unroll
            for (int o = 16; o; o >>= 1) {
                a0 += __shfl_down_sync(0xffffffffu, a0, o);
                a1 += __shfl_down_sync(0xffffffffu, a1, o);
                a2 += __shfl_down_sync(0xffffffffu, a2, o);
                a3 += __shfl_down_sync(0xffffffffu, a3, o);
            }
            if (lane == 0) {
                g_fwd[(b * 4 + 0) * NN + i] = a0;
                g_fwd[(b * 4 + 1) * NN + i] = a1;
                g_fwd[(b * 4 + 2) * NN + i] = a2;
                g_fwd[(b * 4 + 3) * NN + i] = a3;
            }
        }
    }

    // memory erase/write for rows [ch*16, ch*16+16)
    {
        int n = ch * 16 + (tid >> 4);
        int w0 = (tid & 15) * 4;
        float wwn = sww[n];
        float* Mp = g_M + ((size_t)(b * NN) + n) * WWD + w0;
        #pragma unroll
        for (int q = 0; q < 4; q++)
            Mp[q] = Mp[q] * (1.f - wwn * er[w0 + q]) + wwn * vv[w0 + q];
    }
}

// -------------------- K4: per-batch read combine (grid 16, block 256) ----------
__global__ void __launch_bounds__(256) k_read2(int t) {
    int b = blockIdx.x;
    int tid = threadIdx.x;
    __shared__ float kn[RR][WWD];
    __shared__ float wr_s[RR][NN];
    __shared__ float red[64];
    __shared__ float betas[RR], knorm[RR], mbv[RR], mfv[RR], mcv[RR];

    const float* itf = g_itf + (size_t)b * ITFD;

    {
        int r = tid >> 6, w = tid & 63;
        kn[r][w] = itf[O_RK + r * WWD + w];
    }
    __syncthreads();
    if (tid < RR) {
        float ss2 = 0.f;
        for (int w = 0; w < WWD; w++) ss2 += kn[tid][w] * kn[tid][w];
        knorm[tid] = sqrtf(ss2) + EPSF;
        betas[tid] = oneplusf(itf[O_RS + tid]);
        float m0 = itf[O_MO + tid * 3 + 0];
        float m1 = itf[O_MO + tid * 3 + 1];
        float m2 = itf[O_MO + tid * 3 + 2];
        float mxm = fmaxf(m0, fmaxf(m1, m2));
        float e0 = expf(m0 - mxm), e1 = expf(m1 - mxm), e2 = expf(m2 - mxm);
        float s = e0 + e1 + e2;
        mbv[tid] = e0 / s; mfv[tid] = e1 / s; mcv[tid] = e2 / s;
    }
    __syncthreads();

    // content read scores on NEW memory (own row)
    const float* Mrow = g_M + ((size_t)(b * NN) + tid) * WWD;
    float d0 = 0.f, d1 = 0.f, d2 = 0.f, d3 = 0.f, ss2 = 0.f;
    #pragma unroll 8
    for (int w = 0; w < WWD; w++) {
        float m = Mrow[w];
        ss2 += m * m;
        d0 += m * kn[0][w]; d1 += m * kn[1][w]; d2 += m * kn[2][w]; d3 += m * kn[3][w];
    }
    float inv = 1.f / (sqrtf(ss2) + EPSF);
    float scv[4], m4[4];
    scv[0] = betas[0] * (d0 / knorm[0]) * inv;
    scv[1] = betas[1] * (d1 / knorm[1]) * inv;
    scv[2] = betas[2] * (d2 / knorm[2]) * inv;
    scv[3] = betas[3] * (d3 / knorm[3]) * inv;
    #pragma unroll
    for (int r = 0; r < 4; r++) m4[r] = scv[r];
    red4op(m4, true, red);
    float e4[4], s4[4];
    #pragma unroll
    for (int r = 0; r < 4; r++) { e4[r] = expf(scv[r] - m4[r]); s4[r] = e4[r]; }
    red4op(s4, false, red);

    // combine bwd partials + fwd + content
    float wrn[4];
    #pragma unroll
    for (int r = 0; r < 4; r++) {
        float bwd = 0.f;
        #pragma unroll
        for (int ch = 0; ch < 16; ch++)
            bwd += g_bwdP[((b * 16 + ch) * 4 + r) * NN + tid];
        float fw = g_fwd[(b * 4 + r) * NN + tid];
        float cr = e4[r] / s4[r];
        wrn[r] = mbv[r] * bwd + mfv[r] * fw + mcv[r] * cr;
    }
    #pragma unroll
    for (int r = 0; r < 4; r++) {
        wr_s[r][tid] = wrn[r];
        g_wr[(b * RR + r) * NN + tid] = wrn[r];
    }
    __syncthreads();

    // read words
    {
        int r = tid >> 6, w = tid & 63;
        float acc = 0.f;
        for (int n2 = 0; n2 < NN; n2++)
            acc += wr_s[r][n2] * g_M[((size_t)(b * NN) + n2) * WWD + w];
        g_rw[(b * RR + r) * WWD + w] = acc;
        g_rwall[((size_t)t * BB + b) * (RR * WWD) + r * WWD + w] = acc;
    }
}

// -------------------- K6: batched output GEMM (verbatim) --------------------
__global__ void k_out(const float* __restrict__ Wout,
                      const float* __restrict__ bout,
                      float* __restrict__ out) {
    __shared__ float As[32][33];
    __shared__ float Bs[32][33];
    int tx = threadIdx.x & 15, ty = threadIdx.x >> 4;
    int tb0 = blockIdx.x * 32, o0 = blockIdx.y * 32;
    float acc00 = 0.f, acc01 = 0.f, acc10 = 0.f, acc11 = 0.f;
    for (int kt = 0; kt < 768; kt += 32) {
        for (int l = threadIdx.x; l < 1024; l += 256) {
            int mi = l >> 5, ki = l & 31;
            int k = kt + ki;
            int tb = tb0 + mi;
            float av = (k < 512) ? g_hall[(size_t)tb * HH + k]
                                 : g_rwall[(size_t)tb * (RR * WWD) + (k - 512)];
            As[mi][ki] = av;
            Bs[mi][ki] = Wout[(size_t)(o0 + mi) * 768 + k];
        }
        __syncthreads();
        #pragma unroll 8
        for (int ki = 0; ki < 32; ki++) {
            float a0 = As[ty * 2][ki], a1 = As[ty * 2 + 1][ki];
            float b0 = Bs[tx * 2][ki], b1 = Bs[tx * 2 + 1][ki];
            acc00 += a0 * b0; acc01 += a0 * b1;
            acc10 += a1 * b0; acc11 += a1 * b1;
        }
        __syncthreads();
    }
    int tb = tb0 + ty * 2, o = o0 + tx * 2;
    float bo0 = bout[o], bo1 = bout[o + 1];
    out[(size_t)tb * OUTD + o] = acc00 + bo0;
    out[(size_t)tb * OUTD + o + 1] = acc01 + bo1;
    out[(size_t)(tb + 1) * OUTD + o] = acc10 + bo0;
    out[(size_t)(tb + 1) * OUTD + o + 1] = acc11 + bo1;
}

// -------------------- host launch --------------------
extern "C" void kernel_launch(void* const* d_in, const int* in_sizes, int n_in,
                              void* d_out, int out_size) {
    const float* x    = (const float*)d_in[0];
    const float* Wih  = (const float*)d_in[1];
    const float* Whh  = (const float*)d_in[2];
    const float* bih  = (const float*)d_in[3];
    const float* bhh  = (const float*)d_in[4];
    const float* Wint = (const float*)d_in[5];
    const float* bint = (const float*)d_in[6];
    const float* Wout = (const float*)d_in[7];
    const float* bout = (const float*)d_in[8];
    float* out = (float*)d_out;

    void* p;
    cudaGetSymbolAddress(&p, g_h);     cudaMemsetAsync(p, 0, sizeof(float) * 2 * BB * HH);
    cudaGetSymbolAddress(&p, g_c);     cudaMemsetAsync(p, 0, sizeof(float) * BB * HH);
    cudaGetSymbolAddress(&p, g_M);     cudaMemsetAsync(p, 0, sizeof(float) * BB * NN * WWD);
    cudaGetSymbolAddress(&p, g_usage); cudaMemsetAsync(p, 0, sizeof(float) * BB * NN);
    cudaGetSymbolAddress(&p, g_link);  cudaMemsetAsync(p, 0, sizeof(float) * BB * NN * NN);
    cudaGetSymbolAddress(&p, g_prec);  cudaMemsetAsync(p, 0, sizeof(float) * 2 * BB * NN);
    cudaGetSymbolAddress(&p, g_wr);    cudaMemsetAsync(p, 0, sizeof(float) * BB * RR * NN);
    cudaGetSymbolAddress(&p, g_ww);    cudaMemsetAsync(p, 0, sizeof(float) * BB * NN);
    cudaGetSymbolAddress(&p, g_rw);    cudaMemsetAsync(p, 0, sizeof(float) * BB * RR * WWD);

    k_transpose<<<(ITFD * HH + 255) / 256, 256>>>(Wint);

    for (int t = 0; t < TT; t++) {
        int par = t & 1;
        k_lstm<<<128, 256>>>(x, Wih, Whh, bih, bhh, t, par);
        k_itfw<<<16, 256>>>(bint, par);
        k_mem2<<<256, 256>>>(par);
        k_read2<<<16, 256>>>(t);
    }
    k_out<<<dim3(32, 8), 256>>>(Wout, bout, out);
}

// round 10
// speedup vs baseline: 2.4447x; 1.1947x over previous
#include <cuda_runtime.h>
#include <math.h>

#define BB    16
#define TT    64
#define IND   256
#define HH    512
#define NN    256
#define WWD   64
#define RR    4
#define OUTD  256
#define ITFD  471
#define G4H   2048   // 4*H
#define RLEN  768    // recurrent dot length: 256 (rw) + 512 (h)

// interface vector offsets
#define O_RK 0
#define O_RS 256
#define O_WK 260
#define O_WS 324
#define O_ER 325
#define O_WV 389
#define O_FG 453
#define O_AG 457
#define O_WG 458
#define O_MO 459
#define EPSF 1e-6f

// -------------------- persistent state --------------------
__device__ __align__(16) float g_h[2][BB * HH];
__device__ __align__(16) float g_c[BB * HH];
__device__ __align__(16) float g_M[BB * NN * WWD];
__device__ __align__(16) float g_usage[BB * NN];
__device__ __align__(16) float g_link[BB * NN * NN];
__device__ __align__(16) float g_prec[2][BB * NN];
__device__ __align__(16) float g_wr[BB * RR * NN];
__device__ __align__(16) float g_ww[BB * NN];
__device__ __align__(16) float g_rw[BB * RR * WWD];
__device__ __align__(16) float g_itf[BB * ITFD];
__device__ __align__(16) float g_hall[TT * BB * HH];
__device__ __align__(16) float g_rwall[TT * BB * RR * WWD];
__device__ __align__(16) float g_WintT[ITFD * HH];
__device__ __align__(16) float g_bwdP[BB * 16 * RR * NN];
__device__ __align__(16) float g_fwd[BB * RR * NN];
__device__ __align__(16) float g_Wrec[G4H * RLEN];       // [2048][768] = [W_ih(rw cols) | W_hh]
__device__ __align__(16) float g_gatesx[TT * BB * G4H];  // x-part of gates + biases

// -------------------- helpers --------------------
__device__ __forceinline__ float sigf(float x) { return 1.f / (1.f + expf(-x)); }
__device__ __forceinline__ float softplusf(float x) {
    return fmaxf(x, 0.f) + log1pf(expf(-fabsf(x)));
}
__device__ __forceinline__ float oneplusf(float x) { return 1.f + softplusf(x); }

__device__ __forceinline__ float blk_max256(float v, float* red, int tid) {
    red[tid] = v; __syncthreads();
    for (int s = 128; s > 0; s >>= 1) {
        if (tid < s) red[tid] = fmaxf(red[tid], red[tid + s]);
        __syncthreads();
    }
    float r = red[0]; __syncthreads();
    return r;
}
__device__ __forceinline__ float blk_sum256(float v, float* red, int tid) {
    red[tid] = v; __syncthreads();
    for (int s = 128; s > 0; s >>= 1) {
        if (tid < s) red[tid] = red[tid] + red[tid + s];
        __syncthreads();
    }
    float r = red[0]; __syncthreads();
    return r;
}

// block reduce 4 values at once (shfl + smem), results broadcast in v[]
__device__ __forceinline__ void red4op(float v[4], bool domax, volatile float* red) {
    int tid = threadIdx.x;
    #pragma unroll
    for (int r = 0; r < 4; r++)
        #pragma unroll
        for (int o = 16; o; o >>= 1) {
            float u = __shfl_xor_sync(0xffffffffu, v[r], o);
            v[r] = domax ? fmaxf(v[r], u) : (v[r] + u);
        }
    if ((tid & 31) == 0) {
        int w = tid >> 5;
        red[w * 4 + 0] = v[0]; red[w * 4 + 1] = v[1];
        red[w * 4 + 2] = v[2]; red[w * 4 + 3] = v[3];
    }
    __syncthreads();
    if (tid == 0) {
        #pragma unroll
        for (int r = 0; r < 4; r++) {
            float a = red[r];
            for (int w = 1; w < 8; w++) {
                float u = red[w * 4 + r];
                a = domax ? fmaxf(a, u) : (a + u);
            }
            red[40 + r] = a;
        }
    }
    __syncthreads();
    v[0] = red[40]; v[1] = red[41]; v[2] = red[42]; v[3] = red[43];
    __syncthreads();
}

// -------------------- prep kernels (one-time) --------------------
__global__ void k_transpose(const float* __restrict__ Wint) {
    int idx = blockIdx.x * 256 + threadIdx.x;
    if (idx < ITFD * HH) {
        int c = idx / HH;
        int k = idx - c * HH;
        g_WintT[idx] = Wint[k * ITFD + c];
    }
}

__global__ void k_prep_wrec(const float* __restrict__ Wih,
                            const float* __restrict__ Whh) {
    int idx = blockIdx.x * 256 + threadIdx.x;
    if (idx < G4H * RLEN) {
        int row = idx / RLEN;
        int c = idx - row * RLEN;
        g_Wrec[idx] = (c < 256) ? Wih[(size_t)row * 512 + 256 + c]
                                : Whh[(size_t)row * 512 + (c - 256)];
    }
}

// gates_x[tb][n] = sum_{k<256} x[tb][k]*Wih[n][k] + bih[n] + bhh[n]
__global__ void k_gatesx(const float* __restrict__ x,
                         const float* __restrict__ Wih,
                         const float* __restrict__ bih,
                         const float* __restrict__ bhh) {
    __shared__ float As[32][33];
    __shared__ float Bs[32][33];
    int tx = threadIdx.x & 15, ty = threadIdx.x >> 4;
    int m0 = blockIdx.x * 32, n0 = blockIdx.y * 32;
    float a00 = 0.f, a01 = 0.f, a10 = 0.f, a11 = 0.f;
    for (int kt = 0; kt < 256; kt += 32) {
        for (int l = threadIdx.x; l < 1024; l += 256) {
            int mi = l >> 5, ki = l & 31;
            As[mi][ki] = x[(size_t)(m0 + mi) * IND + kt + ki];
            Bs[mi][ki] = Wih[(size_t)(n0 + mi) * 512 + kt + ki];
        }
        __syncthreads();
        #pragma unroll 8
        for (int ki = 0; ki < 32; ki++) {
            float x0 = As[ty * 2][ki], x1 = As[ty * 2 + 1][ki];
            float w0 = Bs[tx * 2][ki], w1 = Bs[tx * 2 + 1][ki];
            a00 += x0 * w0; a01 += x0 * w1;
            a10 += x1 * w0; a11 += x1 * w1;
        }
        __syncthreads();
    }
    int m = m0 + ty * 2, n = n0 + tx * 2;
    float c0 = bih[n] + bhh[n], c1 = bih[n + 1] + bhh[n + 1];
    g_gatesx[(size_t)m * G4H + n] = a00 + c0;
    g_gatesx[(size_t)m * G4H + n + 1] = a01 + c1;
    g_gatesx[(size_t)(m + 1) * G4H + n] = a10 + c0;
    g_gatesx[(size_t)(m + 1) * G4H + n + 1] = a11 + c1;
}

// -------------------- K1: LSTM recurrent, float4 (grid 128, block 256) ----------
__device__ __forceinline__ void dotseg(const float4* __restrict__ a4,
                                       const float* __restrict__ w0,
                                       const float* __restrict__ w1,
                                       const float* __restrict__ w2,
                                       const float* __restrict__ w3,
                                       int n4, float acc[4]) {
    const float4* w04 = (const float4*)w0;
    const float4* w14 = (const float4*)w1;
    const float4* w24 = (const float4*)w2;
    const float4* w34 = (const float4*)w3;
    #pragma unroll 4
    for (int q = 0; q < n4; q++) {
        float4 av = a4[q];
        float4 wv;
        wv = w04[q]; acc[0] += av.x * wv.x + av.y * wv.y + av.z * wv.z + av.w * wv.w;
        wv = w14[q]; acc[1] += av.x * wv.x + av.y * wv.y + av.z * wv.z + av.w * wv.w;
        wv = w24[q]; acc[2] += av.x * wv.x + av.y * wv.y + av.z * wv.z + av.w * wv.w;
        wv = w34[q]; acc[3] += av.x * wv.x + av.y * wv.y + av.z * wv.z + av.w * wv.w;
    }
}

__global__ void __launch_bounds__(256) k_lstm(int t, int par) {
    __shared__ float sred[4][256];
    int tid = threadIdx.x;
    int jj = tid >> 6;          // 0..3
    int kc = (tid >> 4) & 3;    // 0..3, each covers 192 of 768 cols
    int b  = tid & 15;
    int j  = blockIdx.x * 4 + jj;

    const float* w0 = g_Wrec + (size_t)(0 * HH + j) * RLEN;
    const float* w1 = g_Wrec + (size_t)(1 * HH + j) * RLEN;
    const float* w2 = g_Wrec + (size_t)(2 * HH + j) * RLEN;
    const float* w3 = g_Wrec + (size_t)(3 * HH + j) * RLEN;

    float acc[4] = {0.f, 0.f, 0.f, 0.f};
    int c0 = kc * 192;
    // rw piece: cols [c0, min(c0+192,256))
    {
        int s = c0, e = (c0 + 192 < 256) ? c0 + 192 : 256;
        if (s < e)
            dotseg((const float4*)(g_rw + b * 256 + s),
                   w0 + s, w1 + s, w2 + s, w3 + s, (e - s) >> 2, acc);
    }
    // h piece: cols [max(c0,256), c0+192)
    {
        int s = (c0 > 256) ? c0 : 256, e = c0 + 192;
        if (s < e)
            dotseg((const float4*)(g_h[par] + b * HH + (s - 256)),
                   w0 + s, w1 + s, w2 + s, w3 + s, (e - s) >> 2, acc);
    }
    sred[0][tid] = acc[0]; sred[1][tid] = acc[1];
    sred[2][tid] = acc[2]; sred[3][tid] = acc[3];
    __syncthreads();
    if (kc == 0) {
        int base = jj * 64 + b;
        const float* gx = g_gatesx + ((size_t)t * BB + b) * G4H;
        float gi = sred[0][base] + sred[0][base + 16] + sred[0][base + 32] + sred[0][base + 48] + gx[0 * HH + j];
        float gf = sred[1][base] + sred[1][base + 16] + sred[1][base + 32] + sred[1][base + 48] + gx[1 * HH + j];
        float gg = sred[2][base] + sred[2][base + 16] + sred[2][base + 32] + sred[2][base + 48] + gx[2 * HH + j];
        float go = sred[3][base] + sred[3][base + 16] + sred[3][base + 32] + sred[3][base + 48] + gx[3 * HH + j];
        float cold = g_c[b * HH + j];
        float cn = sigf(gf) * cold + sigf(gi) * tanhf(gg);
        float hn = sigf(go) * tanhf(cn);
        g_c[b * HH + j] = cn;
        g_h[par ^ 1][b * HH + j] = hn;
        g_hall[((size_t)t * BB + b) * HH + j] = hn;
    }
}

// -------------------- K2: fused interface GEMV + write addressing (R9 verbatim) -
__global__ void __launch_bounds__(256) k_itfw(const float* __restrict__ bint, int par) {
    int b = blockIdx.x;
    int tid = threadIdx.x;
    __shared__ float hS[HH];
    __shared__ float itfs[ITFD + 1];
    __shared__ float uval[NN];
    __shared__ int   uidx[NN];
    __shared__ float allocv[NN];
    __shared__ float red[NN];
    __shared__ float karr[WWD];
    __shared__ float sc_knorm, sc_beta;

    for (int i = tid; i < HH; i += 256) hS[i] = g_h[par ^ 1][b * HH + i];
    __syncthreads();

    {
        int warp = tid >> 5, lane = tid & 31;
        const float4* h4 = (const float4*)hS;
        for (int c = warp; c < ITFD; c += 8) {
            const float4* w4 = (const float4*)(g_WintT + (size_t)c * HH);
            float acc = 0.f;
            #pragma unroll
            for (int q = 0; q < 4; q++) {
                float4 wv = w4[lane + q * 32];
                float4 hv = h4[lane + q * 32];
                acc += wv.x * hv.x + wv.y * hv.y + wv.z * hv.z + wv.w * hv.w;
            }
            #pragma unroll
            for (int o = 16; o; o >>= 1) acc += __shfl_xor_sync(0xffffffffu, acc, o);
            if (lane == 0) {
                float v = acc + bint[c];
                itfs[c] = v;
                g_itf[b * ITFD + c] = v;
            }
        }
    }
    __syncthreads();

    float fg0 = sigf(itfs[O_FG + 0]);
    float fg1 = sigf(itfs[O_FG + 1]);
    float fg2 = sigf(itfs[O_FG + 2]);
    float fg3 = sigf(itfs[O_FG + 3]);
    float ag  = sigf(itfs[O_AG]);
    float wg  = sigf(itfs[O_WG]);

    int n = tid;
    float psi = 1.f;
    psi *= (1.f - fg0 * g_wr[(b * RR + 0) * NN + n]);
    psi *= (1.f - fg1 * g_wr[(b * RR + 1) * NN + n]);
    psi *= (1.f - fg2 * g_wr[(b * RR + 2) * NN + n]);
    psi *= (1.f - fg3 * g_wr[(b * RR + 3) * NN + n]);
    float u = g_usage[b * NN + n];
    float wagg = g_ww[b * NN + n];  // NW=1
    float un = (u + wagg - u * wagg) * psi;
    g_usage[b * NN + n] = un;

    if (tid < WWD) karr[tid] = itfs[O_WK + tid];
    __syncthreads();
    if (tid == 0) {
        float ss = 0.f;
        for (int w = 0; w < WWD; w++) ss += karr[w] * karr[w];
        sc_knorm = sqrtf(ss) + EPSF;
        sc_beta  = oneplusf(itfs[O_WS]);
    }
    __syncthreads();

    float dot = 0.f, ss = 0.f;
    const float* Mrow = g_M + ((size_t)(b * NN) + n) * WWD;
    #pragma unroll 8
    for (int w = 0; w < WWD; w++) {
        float m = Mrow[w];
        dot += m * karr[w];
        ss += m * m;
    }
    float sim = (dot / sc_knorm) / (sqrtf(ss) + EPSF);
    float sco = sc_beta * sim;
    float mx = blk_max256(sco, red, tid);
    float e = expf(sco - mx);
    float sm = blk_sum256(e, red, tid);
    float cwv = e / sm;

    // stable bitonic sort ascending on (usage, index); shfl for jmp<32
    float v = un; int ix = tid;
    for (int k2 = 2; k2 <= NN; k2 <<= 1) {
        for (int jmp = k2 >> 1; jmp; jmp >>= 1) {
            bool up = ((tid & k2) == 0);
            float v2; int i2;
            if (jmp >= 32) {
                uval[tid] = v; uidx[tid] = ix;
                __syncthreads();
                v2 = uval[tid ^ jmp]; i2 = uidx[tid ^ jmp];
                __syncthreads();
            } else {
                v2 = __shfl_xor_sync(0xffffffffu, v, jmp);
                i2 = __shfl_xor_sync(0xffffffffu, ix, jmp);
            }
            bool lower = ((tid & jmp) == 0);
            bool iless = (v < v2) || (v == v2 && ix < i2);
            bool keep = (iless == (lower == up));
            if (!keep) { v = v2; ix = i2; }
        }
    }

    // exclusive product scan over sorted usage -> allocation
    {
        int lane = tid & 31, wid = tid >> 5;
        float p = v;
        #pragma unroll
        for (int o = 1; o < 32; o <<= 1) {
            float q = __shfl_up_sync(0xffffffffu, p, o);
            if (lane >= o) p *= q;
        }
        if (lane == 31) red[wid] = p;
        __syncthreads();
        if (tid == 0) {
            float a = 1.f;
            #pragma unroll
            for (int w = 0; w < 8; w++) { float q = red[w]; red[8 + w] = a; a *= q; }
        }
        __syncthreads();
        float tmp = __shfl_up_sync(0xffffffffu, p, 1);
        float exclw = (lane == 0) ? 1.f : tmp;
        float excl = red[8 + wid] * exclw;
        allocv[ix] = (1.f - v) * excl;
        __syncthreads();
    }

    float wwn = wg * (ag * allocv[tid] + (1.f - ag) * cwv);
    g_ww[b * NN + tid] = wwn;
    float wsum = blk_sum256(wwn, red, tid);
    float pold = g_prec[par][b * NN + tid];
    g_prec[par ^ 1][b * NN + tid] = (1.f - wsum) * pold + wwn;
}

// -------------------- K3: wide link+M update with fused bwd/fwd (R9 verbatim) ---
__global__ void __launch_bounds__(256) k_mem2(int par) {
    int blk = blockIdx.x;
    int b = blk >> 4, ch = blk & 15;
    int tid = threadIdx.x;
    __shared__ float sww[NN];
    __shared__ float sprec[NN];
    __shared__ float wr4[4][NN];
    __shared__ float er[WWD];
    __shared__ float vv[WWD];
    __shared__ float tile[16][260];

    sww[tid]   = g_ww[b * NN + tid];
    sprec[tid] = g_prec[par][b * NN + tid];
    #pragma unroll
    for (int r = 0; r < RR; r++) wr4[r][tid] = g_wr[(b * RR + r) * NN + tid];
    if (tid < WWD) {
        er[tid] = sigf(g_itf[b * ITFD + O_ER + tid]);
        vv[tid] = sigf(g_itf[b * ITFD + O_WV + tid]);
    }
    __syncthreads();

    float wwj = sww[tid];
    float prj = sprec[tid];
    float bp0 = 0.f, bp1 = 0.f, bp2 = 0.f, bp3 = 0.f;
    float* lbase = g_link + (size_t)b * (NN * NN);
    #pragma unroll 4
    for (int ii = 0; ii < 16; ii++) {
        int i = ch * 16 + ii;
        float wwi = sww[i];
        float l = lbase[(size_t)i * NN + tid];
        float nv = (1.f - wwi - wwj) * l + wwi * prj;
        if (i == tid) nv = 0.f;
        lbase[(size_t)i * NN + tid] = nv;
        tile[ii][tid] = nv;
        bp0 += nv * wr4[0][i];
        bp1 += nv * wr4[1][i];
        bp2 += nv * wr4[2][i];
        bp3 += nv * wr4[3][i];
    }
    g_bwdP[((b * 16 + ch) * 4 + 0) * NN + tid] = bp0;
    g_bwdP[((b * 16 + ch) * 4 + 1) * NN + tid] = bp1;
    g_bwdP[((b * 16 + ch) * 4 + 2) * NN + tid] = bp2;
    g_bwdP[((b * 16 + ch) * 4 + 3) * NN + tid] = bp3;
    __syncthreads();

    {
        int warp = tid >> 5, lane = tid & 31;
        #pragma unroll
        for (int q = 0; q < 2; q++) {
            int ii = warp * 2 + q;
            int i = ch * 16 + ii;
            float a0 = 0.f, a1 = 0.f, a2 = 0.f, a3 = 0.f;
            #pragma unroll
            for (int p = 0; p < 8; p++) {
                int j = lane + p * 32;
                float lv = tile[ii][j];
                a0 += lv * wr4[0][j]; a1 += lv * wr4[1][j];
                a2 += lv * wr4[2][j]; a3 += lv * wr4[3][j];
            }
            #pragma unroll
            for (int o = 16; o; o >>= 1) {
                a0 += __shfl_down_sync(0xffffffffu, a0, o);
                a1 += __shfl_down_sync(0xffffffffu, a1, o);
                a2 += __shfl_down_sync(0xffffffffu, a2, o);
                a3 += __shfl_down_sync(0xffffffffu, a3, o);
            }
            if (lane == 0) {
                g_fwd[(b * 4 + 0) * NN + i] = a0;
                g_fwd[(b * 4 + 1) * NN + i] = a1;
                g_fwd[(b * 4 + 2) * NN + i] = a2;
                g_fwd[(b * 4 + 3) * NN + i] = a3;
            }
        }
    }

    {
        int n = ch * 16 + (tid >> 4);
        int w0 = (tid & 15) * 4;
        float wwn = sww[n];
        float* Mp = g_M + ((size_t)(b * NN) + n) * WWD + w0;
        #pragma unroll
        for (int q = 0; q < 4; q++)
            Mp[q] = Mp[q] * (1.f - wwn * er[w0 + q]) + wwn * vv[w0 + q];
    }
}

// -------------------- K4: per-batch read combine (R9 verbatim) ------------------
__global__ void __launch_bounds__(256) k_read2(int t) {
    int b = blockIdx.x;
    int tid = threadIdx.x;
    __shared__ float kn[RR][WWD];
    __shared__ float wr_s[RR][NN];
    __shared__ float red[64];
    __shared__ float betas[RR], knorm[RR], mbv[RR], mfv[RR], mcv[RR];

    const float* itf = g_itf + (size_t)b * ITFD;

    {
        int r = tid >> 6, w = tid & 63;
        kn[r][w] = itf[O_RK + r * WWD + w];
    }
    __syncthreads();
    if (tid < RR) {
        float ss2 = 0.f;
        for (int w = 0; w < WWD; w++) ss2 += kn[tid][w] * kn[tid][w];
        knorm[tid] = sqrtf(ss2) + EPSF;
        betas[tid] = oneplusf(itf[O_RS + tid]);
        float m0 = itf[O_MO + tid * 3 + 0];
        float m1 = itf[O_MO + tid * 3 + 1];
        float m2 = itf[O_MO + tid * 3 + 2];
        float mxm = fmaxf(m0, fmaxf(m1, m2));
        float e0 = expf(m0 - mxm), e1 = expf(m1 - mxm), e2 = expf(m2 - mxm);
        float s = e0 + e1 + e2;
        mbv[tid] = e0 / s; mfv[tid] = e1 / s; mcv[tid] = e2 / s;
    }
    __syncthreads();

    const float* Mrow = g_M + ((size_t)(b * NN) + tid) * WWD;
    float d0 = 0.f, d1 = 0.f, d2 = 0.f, d3 = 0.f, ss2 = 0.f;
    #pragma unroll 8
    for (int w = 0; w < WWD; w++) {
        float m = Mrow[w];
        ss2 += m * m;
        d0 += m * kn[0][w]; d1 += m * kn[1][w]; d2 += m * kn[2][w]; d3 += m * kn[3][w];
    }
    float inv = 1.f / (sqrtf(ss2) + EPSF);
    float scv[4], m4[4];
    scv[0] = betas[0] * (d0 / knorm[0]) * inv;
    scv[1] = betas[1] * (d1 / knorm[1]) * inv;
    scv[2] = betas[2] * (d2 / knorm[2]) * inv;
    scv[3] = betas[3] * (d3 / knorm[3]) * inv;
    #pragma unroll
    for (int r = 0; r < 4; r++) m4[r] = scv[r];
    red4op(m4, true, red);
    float e4[4], s4[4];
    #pragma unroll
    for (int r = 0; r < 4; r++) { e4[r] = expf(scv[r] - m4[r]); s4[r] = e4[r]; }
    red4op(s4, false, red);

    float wrn[4];
    #pragma unroll
    for (int r = 0; r < 4; r++) {
        float bwd = 0.f;
        #pragma unroll
        for (int ch = 0; ch < 16; ch++)
            bwd += g_bwdP[((b * 16 + ch) * 4 + r) * NN + tid];
        float fw = g_fwd[(b * 4 + r) * NN + tid];
        float cr = e4[r] / s4[r];
        wrn[r] = mbv[r] * bwd + mfv[r] * fw + mcv[r] * cr;
    }
    #pragma unroll
    for (int r = 0; r < 4; r++) {
        wr_s[r][tid] = wrn[r];
        g_wr[(b * RR + r) * NN + tid] = wrn[r];
    }
    __syncthreads();

    {
        int r = tid >> 6, w = tid & 63;
        float acc = 0.f;
        for (int n2 = 0; n2 < NN; n2++)
            acc += wr_s[r][n2] * g_M[((size_t)(b * NN) + n2) * WWD + w];
        g_rw[(b * RR + r) * WWD + w] = acc;
        g_rwall[((size_t)t * BB + b) * (RR * WWD) + r * WWD + w] = acc;
    }
}

// -------------------- K6: batched output GEMM (verbatim) --------------------
__global__ void k_out(const float* __restrict__ Wout,
                      const float* __restrict__ bout,
                      float* __restrict__ out) {
    __shared__ float As[32][33];
    __shared__ float Bs[32][33];
    int tx = threadIdx.x & 15, ty = threadIdx.x >> 4;
    int tb0 = blockIdx.x * 32, o0 = blockIdx.y * 32;
    float acc00 = 0.f, acc01 = 0.f, acc10 = 0.f, acc11 = 0.f;
    for (int kt = 0; kt < 768; kt += 32) {
        for (int l = threadIdx.x; l < 1024; l += 256) {
            int mi = l >> 5, ki = l & 31;
            int k = kt + ki;
            int tb = tb0 + mi;
            float av = (k < 512) ? g_hall[(size_t)tb * HH + k]
                                 : g_rwall[(size_t)tb * (RR * WWD) + (k - 512)];
            As[mi][ki] = av;
            Bs[mi][ki] = Wout[(size_t)(o0 + mi) * 768 + k];
        }
        __syncthreads();
        #pragma unroll 8
        for (int ki = 0; ki < 32; ki++) {
            float a0 = As[ty * 2][ki], a1 = As[ty * 2 + 1][ki];
            float b0 = Bs[tx * 2][ki], b1 = Bs[tx * 2 + 1][ki];
            acc00 += a0 * b0; acc01 += a0 * b1;
            acc10 += a1 * b0; acc11 += a1 * b1;
        }
        __syncthreads();
    }
    int tb = tb0 + ty * 2, o = o0 + tx * 2;
    float bo0 = bout[o], bo1 = bout[o + 1];
    out[(size_t)tb * OUTD + o] = acc00 + bo0;
    out[(size_t)tb * OUTD + o + 1] = acc01 + bo1;
    out[(size_t)(tb + 1) * OUTD + o] = acc10 + bo0;
    out[(size_t)(tb + 1) * OUTD + o + 1] = acc11 + bo1;
}

// -------------------- host launch --------------------
extern "C" void kernel_launch(void* const* d_in, const int* in_sizes, int n_in,
                              void* d_out, int out_size) {
    const float* x    = (const float*)d_in[0];
    const float* Wih  = (const float*)d_in[1];
    const float* Whh  = (const float*)d_in[2];
    const float* bih  = (const float*)d_in[3];
    const float* bhh  = (const float*)d_in[4];
    const float* Wint = (const float*)d_in[5];
    const float* bint = (const float*)d_in[6];
    const float* Wout = (const float*)d_in[7];
    const float* bout = (const float*)d_in[8];
    float* out = (float*)d_out;

    void* p;
    cudaGetSymbolAddress(&p, g_h);     cudaMemsetAsync(p, 0, sizeof(float) * 2 * BB * HH);
    cudaGetSymbolAddress(&p, g_c);     cudaMemsetAsync(p, 0, sizeof(float) * BB * HH);
    cudaGetSymbolAddress(&p, g_M);     cudaMemsetAsync(p, 0, sizeof(float) * BB * NN * WWD);
    cudaGetSymbolAddress(&p, g_usage); cudaMemsetAsync(p, 0, sizeof(float) * BB * NN);
    cudaGetSymbolAddress(&p, g_link);  cudaMemsetAsync(p, 0, sizeof(float) * BB * NN * NN);
    cudaGetSymbolAddress(&p, g_prec);  cudaMemsetAsync(p, 0, sizeof(float) * 2 * BB * NN);
    cudaGetSymbolAddress(&p, g_wr);    cudaMemsetAsync(p, 0, sizeof(float) * BB * RR * NN);
    cudaGetSymbolAddress(&p, g_ww);    cudaMemsetAsync(p, 0, sizeof(float) * BB * NN);
    cudaGetSymbolAddress(&p, g_rw);    cudaMemsetAsync(p, 0, sizeof(float) * BB * RR * WWD);

    k_transpose<<<(ITFD * HH + 255) / 256, 256>>>(Wint);
    k_prep_wrec<<<(G4H * RLEN + 255) / 256, 256>>>(Wih, Whh);
    k_gatesx<<<dim3(32, 64), 256>>>(x, Wih, bih, bhh);

    for (int t = 0; t < TT; t++) {
        int par = t & 1;
        k_lstm<<<128, 256>>>(t, par);
        k_itfw<<<16, 256>>>(bint, par);
        k_mem2<<<256, 256>>>(par);
        k_read2<<<16, 256>>>(t);
    }
    k_out<<<dim3(32, 8), 256>>>(Wout, bout, out);
}

// round 11
// speedup vs baseline: 4.3537x; 1.7809x over previous
#include <cuda_runtime.h>
#include <math.h>

#define BB    16
#define TT    64
#define IND   256
#define HH    512
#define NN    256
#define WWD   64
#define RR    4
#define OUTD  256
#define ITFD  471
#define G4H   2048   // 4*H
#define RLEN  768    // combined activation row: 256 (rw) + 512 (h)

// interface vector offsets
#define O_RK 0
#define O_RS 256
#define O_WK 260
#define O_WS 324
#define O_ER 325
#define O_WV 389
#define O_FG 453
#define O_AG 457
#define O_WG 458
#define O_MO 459
#define EPSF 1e-6f

// -------------------- persistent state --------------------
__device__ __align__(16) float g_act[2][BB * RLEN];   // [rw(256) | h(512)] per batch
__device__ __align__(16) float g_c[BB * HH];
__device__ __align__(16) float g_M[BB * NN * WWD];
__device__ __align__(16) float g_usage[BB * NN];
__device__ __align__(16) float g_link[BB * NN * NN];
__device__ __align__(16) float g_prec[2][BB * NN];
__device__ __align__(16) float g_wr[BB * RR * NN];
__device__ __align__(16) float g_ww[BB * NN];
__device__ __align__(16) float g_itf[BB * ITFD];
__device__ __align__(16) float g_hall[TT * BB * HH];
__device__ __align__(16) float g_rwall[TT * BB * RR * WWD];
__device__ __align__(16) float g_WintT[ITFD * HH];
__device__ __align__(16) float g_bwdP[BB * 16 * RR * NN];
__device__ __align__(16) float g_fwd[BB * RR * NN];
__device__ __align__(16) float g_Wrec[G4H * RLEN];       // [2048][768] = [W_ih(rw cols) | W_hh]
__device__ __align__(16) float g_gatesx[TT * BB * G4H];  // x-part of gates + biases

// -------------------- helpers --------------------
__device__ __forceinline__ float sigf(float x) { return 1.f / (1.f + expf(-x)); }
__device__ __forceinline__ float softplusf(float x) {
    return fmaxf(x, 0.f) + log1pf(expf(-fabsf(x)));
}
__device__ __forceinline__ float oneplusf(float x) { return 1.f + softplusf(x); }

__device__ __forceinline__ float blk_max256(float v, float* red, int tid) {
    red[tid] = v; __syncthreads();
    for (int s = 128; s > 0; s >>= 1) {
        if (tid < s) red[tid] = fmaxf(red[tid], red[tid + s]);
        __syncthreads();
    }
    float r = red[0]; __syncthreads();
    return r;
}
__device__ __forceinline__ float blk_sum256(float v, float* red, int tid) {
    red[tid] = v; __syncthreads();
    for (int s = 128; s > 0; s >>= 1) {
        if (tid < s) red[tid] = red[tid] + red[tid + s];
        __syncthreads();
    }
    float r = red[0]; __syncthreads();
    return r;
}

__device__ __forceinline__ void red4op(float v[4], bool domax, volatile float* red) {
    int tid = threadIdx.x;
    #pragma unroll
    for (int r = 0; r < 4; r++)
        #pragma unroll
        for (int o = 16; o; o >>= 1) {
            float u = __shfl_xor_sync(0xffffffffu, v[r], o);
            v[r] = domax ? fmaxf(v[r], u) : (v[r] + u);
        }
    if ((tid & 31) == 0) {
        int w = tid >> 5;
        red[w * 4 + 0] = v[0]; red[w * 4 + 1] = v[1];
        red[w * 4 + 2] = v[2]; red[w * 4 + 3] = v[3];
    }
    __syncthreads();
    if (tid == 0) {
        #pragma unroll
        for (int r = 0; r < 4; r++) {
            float a = red[r];
            for (int w = 1; w < 8; w++) {
                float u = red[w * 4 + r];
                a = domax ? fmaxf(a, u) : (a + u);
            }
            red[40 + r] = a;
        }
    }
    __syncthreads();
    v[0] = red[40]; v[1] = red[41]; v[2] = red[42]; v[3] = red[43];
    __syncthreads();
}

// -------------------- prep kernels (one-time) --------------------
__global__ void k_transpose(const float* __restrict__ Wint) {
    int idx = blockIdx.x * 256 + threadIdx.x;
    if (idx < ITFD * HH) {
        int c = idx / HH;
        int k = idx - c * HH;
        g_WintT[idx] = Wint[(size_t)k * ITFD + c];
    }
}

__global__ void k_prep_wrec(const float* __restrict__ Wih,
                            const float* __restrict__ Whh) {
    int idx = blockIdx.x * 256 + threadIdx.x;
    if (idx < G4H * RLEN) {
        int row = idx / RLEN;
        int c = idx - row * RLEN;
        g_Wrec[idx] = (c < 256) ? Wih[(size_t)row * 512 + 256 + c]
                                : Whh[(size_t)row * 512 + (c - 256)];
    }
}

__global__ void k_gatesx(const float* __restrict__ x,
                         const float* __restrict__ Wih,
                         const float* __restrict__ bih,
                         const float* __restrict__ bhh) {
    __shared__ float As[32][33];
    __shared__ float Bs[32][33];
    int tx = threadIdx.x & 15, ty = threadIdx.x >> 4;
    int m0 = blockIdx.x * 32, n0 = blockIdx.y * 32;
    float a00 = 0.f, a01 = 0.f, a10 = 0.f, a11 = 0.f;
    for (int kt = 0; kt < 256; kt += 32) {
        for (int l = threadIdx.x; l < 1024; l += 256) {
            int mi = l >> 5, ki = l & 31;
            As[mi][ki] = x[(size_t)(m0 + mi) * IND + kt + ki];
            Bs[mi][ki] = Wih[(size_t)(n0 + mi) * 512 + kt + ki];
        }
        __syncthreads();
        #pragma unroll 8
        for (int ki = 0; ki < 32; ki++) {
            float x0 = As[ty * 2][ki], x1 = As[ty * 2 + 1][ki];
            float w0 = Bs[tx * 2][ki], w1 = Bs[tx * 2 + 1][ki];
            a00 += x0 * w0; a01 += x0 * w1;
            a10 += x1 * w0; a11 += x1 * w1;
        }
        __syncthreads();
    }
    int m = m0 + ty * 2, n = n0 + tx * 2;
    float c0 = bih[n] + bhh[n], c1 = bih[n + 1] + bhh[n + 1];
    g_gatesx[(size_t)m * G4H + n] = a00 + c0;
    g_gatesx[(size_t)m * G4H + n + 1] = a01 + c1;
    g_gatesx[(size_t)(m + 1) * G4H + n] = a10 + c0;
    g_gatesx[(size_t)(m + 1) * G4H + n + 1] = a11 + c1;
}

// -------------------- K1: LSTM recurrent, grid 512 (1 j per block) --------------
// tid = kc*16 + b; kc covers 48 contiguous cols of the 768-wide combined act row.
__global__ void __launch_bounds__(256) k_lstm(int t, int par) {
    __shared__ float sgate[4][8][16];
    __shared__ float gfin[4][16];
    int tid = threadIdx.x;
    int kc = tid >> 4;      // 0..15
    int b  = tid & 15;
    int j  = blockIdx.x;    // 0..511

    int c0 = kc * 48;
    const float4* a4  = (const float4*)(g_act[par] + b * RLEN + c0);
    const float4* w04 = (const float4*)(g_Wrec + (size_t)(0 * HH + j) * RLEN + c0);
    const float4* w14 = (const float4*)(g_Wrec + (size_t)(1 * HH + j) * RLEN + c0);
    const float4* w24 = (const float4*)(g_Wrec + (size_t)(2 * HH + j) * RLEN + c0);
    const float4* w34 = (const float4*)(g_Wrec + (size_t)(3 * HH + j) * RLEN + c0);

    float acc0 = 0.f, acc1 = 0.f, acc2 = 0.f, acc3 = 0.f;
    #pragma unroll
    for (int q = 0; q < 12; q++) {
        float4 av = a4[q];
        float4 wv;
        wv = w04[q]; acc0 += av.x * wv.x + av.y * wv.y + av.z * wv.z + av.w * wv.w;
        wv = w14[q]; acc1 += av.x * wv.x + av.y * wv.y + av.z * wv.z + av.w * wv.w;
        wv = w24[q]; acc2 += av.x * wv.x + av.y * wv.y + av.z * wv.z + av.w * wv.w;
        wv = w34[q]; acc3 += av.x * wv.x + av.y * wv.y + av.z * wv.z + av.w * wv.w;
    }
    // combine kc pairs within warp (lanes 16 apart share (kc, kc^1))
    acc0 += __shfl_xor_sync(0xffffffffu, acc0, 16);
    acc1 += __shfl_xor_sync(0xffffffffu, acc1, 16);
    acc2 += __shfl_xor_sync(0xffffffffu, acc2, 16);
    acc3 += __shfl_xor_sync(0xffffffffu, acc3, 16);
    int w = tid >> 5;
    if ((tid & 16) == 0) {
        sgate[0][w][b] = acc0; sgate[1][w][b] = acc1;
        sgate[2][w][b] = acc2; sgate[3][w][b] = acc3;
    }
    __syncthreads();
    if (tid < 64) {
        int g = tid >> 4, bb = tid & 15;
        float s = 0.f;
        #pragma unroll
        for (int w2 = 0; w2 < 8; w2++) s += sgate[g][w2][bb];
        gfin[g][bb] = s;
    }
    __syncthreads();
    if (tid < 16) {
        int bb = tid;
        const float* gx = g_gatesx + ((size_t)t * BB + bb) * G4H;
        float gi = gfin[0][bb] + gx[0 * HH + j];
        float gf = gfin[1][bb] + gx[1 * HH + j];
        float gg = gfin[2][bb] + gx[2 * HH + j];
        float go = gfin[3][bb] + gx[3 * HH + j];
        float cold = g_c[bb * HH + j];
        float cn = sigf(gf) * cold + sigf(gi) * tanhf(gg);
        float hn = sigf(go) * tanhf(cn);
        g_c[bb * HH + j] = cn;
        g_act[par ^ 1][bb * RLEN + 256 + j] = hn;
        g_hall[((size_t)t * BB + bb) * HH + j] = hn;
    }
}

// -------------------- K2: wide interface GEMV (grid 118, block 256) -------------
// block covers 4 cols x 16 batches; h staged in smem; each weight col read once.
__global__ void __launch_bounds__(256) k_itf2(const float* __restrict__ bint, int par) {
    __shared__ float hS[16 * 512];
    int tid = threadIdx.x;
    // stage h (offset 256 within each 768-row)
    for (int i = tid; i < 2048; i += 256) {      // 2048 float4
        int b = i >> 7, q = i & 127;
        ((float4*)hS)[i] = ((const float4*)(g_act[par ^ 1] + b * RLEN + 256))[q];
    }
    __syncthreads();

    int lane = tid & 31, w = tid >> 5;
    int cbase = blockIdx.x * 4;
    #pragma unroll
    for (int i = 0; i < 8; i++) {
        int task = i * 8 + w;          // 64 tasks: (ci, b)
        int c = cbase + (task >> 4);
        int b = task & 15;
        if (c < ITFD) {
            const float4* w4 = (const float4*)(g_WintT + (size_t)c * HH);
            const float4* h4 = (const float4*)(hS + b * 512);
            float acc = 0.f;
            #pragma unroll
            for (int q = 0; q < 4; q++) {
                float4 wv = w4[lane + q * 32];
                float4 hv = h4[lane + q * 32];
                acc += wv.x * hv.x + wv.y * hv.y + wv.z * hv.z + wv.w * hv.w;
            }
            #pragma unroll
            for (int o = 16; o; o >>= 1) acc += __shfl_xor_sync(0xffffffffu, acc, o);
            if (lane == 0) g_itf[b * ITFD + c] = acc + bint[c];
        }
    }
}

// -------------------- K3: per-batch write addressing (grid 16) ------------------
__global__ void __launch_bounds__(256) k_write(int par) {
    int b = blockIdx.x;
    int tid = threadIdx.x;
    __shared__ float itfs[ITFD + 1];
    __shared__ float uval[NN];
    __shared__ int   uidx[NN];
    __shared__ float allocv[NN];
    __shared__ float red[NN];
    __shared__ float karr[WWD];
    __shared__ float sc_knorm, sc_beta;

    for (int i = tid; i < ITFD; i += 256) itfs[i] = g_itf[b * ITFD + i];
    __syncthreads();

    float fg0 = sigf(itfs[O_FG + 0]);
    float fg1 = sigf(itfs[O_FG + 1]);
    float fg2 = sigf(itfs[O_FG + 2]);
    float fg3 = sigf(itfs[O_FG + 3]);
    float ag  = sigf(itfs[O_AG]);
    float wg  = sigf(itfs[O_WG]);

    int n = tid;
    float psi = 1.f;
    psi *= (1.f - fg0 * g_wr[(b * RR + 0) * NN + n]);
    psi *= (1.f - fg1 * g_wr[(b * RR + 1) * NN + n]);
    psi *= (1.f - fg2 * g_wr[(b * RR + 2) * NN + n]);
    psi *= (1.f - fg3 * g_wr[(b * RR + 3) * NN + n]);
    float u = g_usage[b * NN + n];
    float wagg = g_ww[b * NN + n];  // NW=1
    float un = (u + wagg - u * wagg) * psi;
    g_usage[b * NN + n] = un;

    if (tid < WWD) karr[tid] = itfs[O_WK + tid];
    __syncthreads();
    if (tid == 0) {
        float ss = 0.f;
        for (int w = 0; w < WWD; w++) ss += karr[w] * karr[w];
        sc_knorm = sqrtf(ss) + EPSF;
        sc_beta  = oneplusf(itfs[O_WS]);
    }
    __syncthreads();

    // content write scores (OLD memory)
    float dot = 0.f, ss = 0.f;
    const float* Mrow = g_M + ((size_t)(b * NN) + n) * WWD;
    #pragma unroll 8
    for (int w = 0; w < WWD; w++) {
        float m = Mrow[w];
        dot += m * karr[w];
        ss += m * m;
    }
    float sim = (dot / sc_knorm) / (sqrtf(ss) + EPSF);
    float sco = sc_beta * sim;
    float mx = blk_max256(sco, red, tid);
    float e = expf(sco - mx);
    float sm = blk_sum256(e, red, tid);
    float cwv = e / sm;

    // stable bitonic sort ascending on (usage, index); shfl for jmp<32
    float v = un; int ix = tid;
    for (int k2 = 2; k2 <= NN; k2 <<= 1) {
        for (int jmp = k2 >> 1; jmp; jmp >>= 1) {
            bool up = ((tid & k2) == 0);
            float v2; int i2;
            if (jmp >= 32) {
                uval[tid] = v; uidx[tid] = ix;
                __syncthreads();
                v2 = uval[tid ^ jmp]; i2 = uidx[tid ^ jmp];
                __syncthreads();
            } else {
                v2 = __shfl_xor_sync(0xffffffffu, v, jmp);
                i2 = __shfl_xor_sync(0xffffffffu, ix, jmp);
            }
            bool lower = ((tid & jmp) == 0);
            bool iless = (v < v2) || (v == v2 && ix < i2);
            bool keep = (iless == (lower == up));
            if (!keep) { v = v2; ix = i2; }
        }
    }

    // exclusive product scan over sorted usage -> allocation
    {
        int lane = tid & 31, wid = tid >> 5;
        float p = v;
        #pragma unroll
        for (int o = 1; o < 32; o <<= 1) {
            float q = __shfl_up_sync(0xffffffffu, p, o);
            if (lane >= o) p *= q;
        }
        if (lane == 31) red[wid] = p;
        __syncthreads();
        if (tid == 0) {
            float a = 1.f;
            #pragma unroll
            for (int w = 0; w < 8; w++) { float q = red[w]; red[8 + w] = a; a *= q; }
        }
        __syncthreads();
        float tmp = __shfl_up_sync(0xffffffffu, p, 1);
        float exclw = (lane == 0) ? 1.f : tmp;
        float excl = red[8 + wid] * exclw;
        allocv[ix] = (1.f - v) * excl;
        __syncthreads();
    }

    float wwn = wg * (ag * allocv[tid] + (1.f - ag) * cwv);
    g_ww[b * NN + tid] = wwn;
    float wsum = blk_sum256(wwn, red, tid);
    float pold = g_prec[par][b * NN + tid];
    g_prec[par ^ 1][b * NN + tid] = (1.f - wsum) * pold + wwn;
}

// -------------------- K4: wide link+M update with fused bwd/fwd (R9 verbatim) ---
__global__ void __launch_bounds__(256) k_mem2(int par) {
    int blk = blockIdx.x;
    int b = blk >> 4, ch = blk & 15;
    int tid = threadIdx.x;
    __shared__ float sww[NN];
    __shared__ float sprec[NN];
    __shared__ float wr4[4][NN];
    __shared__ float er[WWD];
    __shared__ float vv[WWD];
    __shared__ float tile[16][260];

    sww[tid]   = g_ww[b * NN + tid];
    sprec[tid] = g_prec[par][b * NN + tid];
    #pragma unroll
    for (int r = 0; r < RR; r++) wr4[r][tid] = g_wr[(b * RR + r) * NN + tid];
    if (tid < WWD) {
        er[tid] = sigf(g_itf[b * ITFD + O_ER + tid]);
        vv[tid] = sigf(g_itf[b * ITFD + O_WV + tid]);
    }
    __syncthreads();

    float wwj = sww[tid];
    float prj = sprec[tid];
    float bp0 = 0.f, bp1 = 0.f, bp2 = 0.f, bp3 = 0.f;
    float* lbase = g_link + (size_t)b * (NN * NN);
    #pragma unroll 4
    for (int ii = 0; ii < 16; ii++) {
        int i = ch * 16 + ii;
        float wwi = sww[i];
        float l = lbase[(size_t)i * NN + tid];
        float nv = (1.f - wwi - wwj) * l + wwi * prj;
        if (i == tid) nv = 0.f;
        lbase[(size_t)i * NN + tid] = nv;
        tile[ii][tid] = nv;
        bp0 += nv * wr4[0][i];
        bp1 += nv * wr4[1][i];
        bp2 += nv * wr4[2][i];
        bp3 += nv * wr4[3][i];
    }
    g_bwdP[((b * 16 + ch) * 4 + 0) * NN + tid] = bp0;
    g_bwdP[((b * 16 + ch) * 4 + 1) * NN + tid] = bp1;
    g_bwdP[((b * 16 + ch) * 4 + 2) * NN + tid] = bp2;
    g_bwdP[((b * 16 + ch) * 4 + 3) * NN + tid] = bp3;
    __syncthreads();

    {
        int warp = tid >> 5, lane = tid & 31;
        #pragma unroll
        for (int q = 0; q < 2; q++) {
            int ii = warp * 2 + q;
            int i = ch * 16 + ii;
            float a0 = 0.f, a1 = 0.f, a2 = 0.f, a3 = 0.f;
            #pragma unroll
            for (int p = 0; p < 8; p++) {
                int jx = lane + p * 32;
                float lv = tile[ii][jx];
                a0 += lv * wr4[0][jx]; a1 += lv * wr4[1][jx];
                a2 += lv * wr4[2][jx]; a3 += lv * wr4[3][jx];
            }
            #pragma unroll
            for (int o = 16; o; o >>= 1) {
                a0 += __shfl_down_sync(0xffffffffu, a0, o);
                a1 += __shfl_down_sync(0xffffffffu, a1, o);
                a2 += __shfl_down_sync(0xffffffffu, a2, o);
                a3 += __shfl_down_sync(0xffffffffu, a3, o);
            }
            if (lane == 0) {
                g_fwd[(b * 4 + 0) * NN + i] = a0;
                g_fwd[(b * 4 + 1) * NN + i] = a1;
                g_fwd[(b * 4 + 2) * NN + i] = a2;
                g_fwd[(b * 4 + 3) * NN + i] = a3;
            }
        }
    }

    {
        int n = ch * 16 + (tid >> 4);
        int w0 = (tid & 15) * 4;
        float wwn = sww[n];
        float* Mp = g_M + ((size_t)(b * NN) + n) * WWD + w0;
        #pragma unroll
        for (int q = 0; q < 4; q++)
            Mp[q] = Mp[q] * (1.f - wwn * er[w0 + q]) + wwn * vv[w0 + q];
    }
}

// -------------------- K5: per-batch read combine (grid 16) ----------------------
__global__ void __launch_bounds__(256) k_read2(int t, int par) {
    int b = blockIdx.x;
    int tid = threadIdx.x;
    __shared__ float kn[RR][WWD];
    __shared__ float wr_s[RR][NN];
    __shared__ float red[64];
    __shared__ float betas[RR], knorm[RR], mbv[RR], mfv[RR], mcv[RR];

    const float* itf = g_itf + (size_t)b * ITFD;

    {
        int r = tid >> 6, w = tid & 63;
        kn[r][w] = itf[O_RK + r * WWD + w];
    }
    __syncthreads();
    if (tid < RR) {
        float ss2 = 0.f;
        for (int w = 0; w < WWD; w++) ss2 += kn[tid][w] * kn[tid][w];
        knorm[tid] = sqrtf(ss2) + EPSF;
        betas[tid] = oneplusf(itf[O_RS + tid]);
        float m0 = itf[O_MO + tid * 3 + 0];
        float m1 = itf[O_MO + tid * 3 + 1];
        float m2 = itf[O_MO + tid * 3 + 2];
        float mxm = fmaxf(m0, fmaxf(m1, m2));
        float e0 = expf(m0 - mxm), e1 = expf(m1 - mxm), e2 = expf(m2 - mxm);
        float s = e0 + e1 + e2;
        mbv[tid] = e0 / s; mfv[tid] = e1 / s; mcv[tid] = e2 / s;
    }
    __syncthreads();

    const float* Mrow = g_M + ((size_t)(b * NN) + tid) * WWD;
    float d0 = 0.f, d1 = 0.f, d2 = 0.f, d3 = 0.f, ss2 = 0.f;
    #pragma unroll 8
    for (int w = 0; w < WWD; w++) {
        float m = Mrow[w];
        ss2 += m * m;
        d0 += m * kn[0][w]; d1 += m * kn[1][w]; d2 += m * kn[2][w]; d3 += m * kn[3][w];
    }
    float inv = 1.f / (sqrtf(ss2) + EPSF);
    float scv[4], m4[4];
    scv[0] = betas[0] * (d0 / knorm[0]) * inv;
    scv[1] = betas[1] * (d1 / knorm[1]) * inv;
    scv[2] = betas[2] * (d2 / knorm[2]) * inv;
    scv[3] = betas[3] * (d3 / knorm[3]) * inv;
    #pragma unroll
    for (int r = 0; r < 4; r++) m4[r] = scv[r];
    red4op(m4, true, red);
    float e4[4], s4[4];
    #pragma unroll
    for (int r = 0; r < 4; r++) { e4[r] = expf(scv[r] - m4[r]); s4[r] = e4[r]; }
    red4op(s4, false, red);

    float wrn[4];
    #pragma unroll
    for (int r = 0; r < 4; r++) {
        float bwd = 0.f;
        #pragma unroll
        for (int ch = 0; ch < 16; ch++)
            bwd += g_bwdP[((b * 16 + ch) * 4 + r) * NN + tid];
        float fw = g_fwd[(b * 4 + r) * NN + tid];
        float cr = e4[r] / s4[r];
        wrn[r] = mbv[r] * bwd + mfv[r] * fw + mcv[r] * cr;
    }
    #pragma unroll
    for (int r = 0; r < 4; r++) {
        wr_s[r][tid] = wrn[r];
        g_wr[(b * RR + r) * NN + tid] = wrn[r];
    }
    __syncthreads();

    // read words -> combined activation buffer (rw cols [0,256)) + rwall
    {
        int r = tid >> 6, w = tid & 63;
        float acc = 0.f;
        for (int n2 = 0; n2 < NN; n2++)
            acc += wr_s[r][n2] * g_M[((size_t)(b * NN) + n2) * WWD + w];
        g_act[par ^ 1][b * RLEN + r * 64 + w] = acc;
        g_rwall[((size_t)t * BB + b) * (RR * WWD) + r * WWD + w] = acc;
    }
}

// -------------------- K6: batched output GEMM (verbatim) --------------------
__global__ void k_out(const float* __restrict__ Wout,
                      const float* __restrict__ bout,
                      float* __restrict__ out) {
    __shared__ float As[32][33];
    __shared__ float Bs[32][33];
    int tx = threadIdx.x & 15, ty = threadIdx.x >> 4;
    int tb0 = blockIdx.x * 32, o0 = blockIdx.y * 32;
    float acc00 = 0.f, acc01 = 0.f, acc10 = 0.f, acc11 = 0.f;
    for (int kt = 0; kt < 768; kt += 32) {
        for (int l = threadIdx.x; l < 1024; l += 256) {
            int mi = l >> 5, ki = l & 31;
            int k = kt + ki;
            int tb = tb0 + mi;
            float av = (k < 512) ? g_hall[(size_t)tb * HH + k]
                                 : g_rwall[(size_t)tb * (RR * WWD) + (k - 512)];
            As[mi][ki] = av;
            Bs[mi][ki] = Wout[(size_t)(o0 + mi) * 768 + k];
        }
        __syncthreads();
        #pragma unroll 8
        for (int ki = 0; ki < 32; ki++) {
            float a0 = As[ty * 2][ki], a1 = As[ty * 2 + 1][ki];
            float b0 = Bs[tx * 2][ki], b1 = Bs[tx * 2 + 1][ki];
            acc00 += a0 * b0; acc01 += a0 * b1;
            acc10 += a1 * b0; acc11 += a1 * b1;
        }
        __syncthreads();
    }
    int tb = tb0 + ty * 2, o = o0 + tx * 2;
    float bo0 = bout[o], bo1 = bout[o + 1];
    out[(size_t)tb * OUTD + o] = acc00 + bo0;
    out[(size_t)tb * OUTD + o + 1] = acc01 + bo1;
    out[(size_t)(tb + 1) * OUTD + o] = acc10 + bo0;
    out[(size_t)(tb + 1) * OUTD + o + 1] = acc11 + bo1;
}

// -------------------- host launch --------------------
extern "C" void kernel_launch(void* const* d_in, const int* in_sizes, int n_in,
                              void* d_out, int out_size) {
    const float* x    = (const float*)d_in[0];
    const float* Wih  = (const float*)d_in[1];
    const float* Whh  = (const float*)d_in[2];
    const float* bih  = (const float*)d_in[3];
    const float* bhh  = (const float*)d_in[4];
    const float* Wint = (const float*)d_in[5];
    const float* bint = (const float*)d_in[6];
    const float* Wout = (const float*)d_in[7];
    const float* bout = (const float*)d_in[8];
    float* out = (float*)d_out;

    void* p;
    cudaGetSymbolAddress(&p, g_act);   cudaMemsetAsync(p, 0, sizeof(float) * 2 * BB * RLEN);
    cudaGetSymbolAddress(&p, g_c);     cudaMemsetAsync(p, 0, sizeof(float) * BB * HH);
    cudaGetSymbolAddress(&p, g_M);     cudaMemsetAsync(p, 0, sizeof(float) * BB * NN * WWD);
    cudaGetSymbolAddress(&p, g_usage); cudaMemsetAsync(p, 0, sizeof(float) * BB * NN);
    cudaGetSymbolAddress(&p, g_link);  cudaMemsetAsync(p, 0, sizeof(float) * BB * NN * NN);
    cudaGetSymbolAddress(&p, g_prec);  cudaMemsetAsync(p, 0, sizeof(float) * 2 * BB * NN);
    cudaGetSymbolAddress(&p, g_wr);    cudaMemsetAsync(p, 0, sizeof(float) * BB * RR * NN);
    cudaGetSymbolAddress(&p, g_ww);    cudaMemsetAsync(p, 0, sizeof(float) * BB * NN);

    k_transpose<<<(ITFD * HH + 255) / 256, 256>>>(Wint);
    k_prep_wrec<<<(G4H * RLEN + 255) / 256, 256>>>(Wih, Whh);
    k_gatesx<<<dim3(32, 64), 256>>>(x, Wih, bih, bhh);

    for (int t = 0; t < TT; t++) {
        int par = t & 1;
        k_lstm<<<512, 256>>>(t, par);
        k_itf2<<<118, 256>>>(bint, par);
        k_write<<<16, 256>>>(par);
        k_mem2<<<256, 256>>>(par);
        k_read2<<<16, 256>>>(t, par);
    }
    k_out<<<dim3(32, 8), 256>>>(Wout, bout, out);
}